// round 12
// baseline (speedup 1.0000x reference)
#include <cuda_runtime.h>
#include <cuda_fp16.h>
#include <cstdint>

#define NN 100000
#define NE 1600000
#define HH 64
#define NLAYERS 3

// ---------------- device scratch ----------------
__device__ float4 g_h4[NN * 16];     // h: (N, 64) fp32
__device__ float4 g_agg4[NN * 16];   // agg: (N, 64) fp32
__device__ __half2 g_ah[NN * 32];    // a[n] = h[n] @ W1[0:64] + e_b1 (fp16)
__device__ __half2 g_bh[NN * 32];    // b[n] = h[n] @ W1[64:128]      (fp16)
__device__ float4 g_x4[NN];          // padded coords (x,y,z,0)
__device__ float  g_dx[NN * 3];
__device__ float4 g_tmean4[16];

// ---------------- helpers ----------------
__device__ __forceinline__ float siluf(float v) {
    float th;
    float hv = 0.5f * v;
    asm("tanh.approx.f32 %0, %1;" : "=f"(th) : "f"(hv));
    return fmaf(hv, th, hv);
}
__device__ __forceinline__ float silux(float v) {
    return __fdividef(v, 1.0f + __expf(-v));
}
// packed half2 silu: silu(x) = 0.5x + 0.5x*tanh(0.5x)
__device__ __forceinline__ uint32_t silu_h2(uint32_t x) {
    uint32_t hv, th, r;
    asm("mul.rn.f16x2 %0, %1, %2;" : "=r"(hv) : "r"(x), "r"(0x38003800u));
    asm("tanh.approx.f16x2 %0, %1;" : "=r"(th) : "r"(hv));
    asm("fma.rn.f16x2 %0, %1, %2, %3;" : "=r"(r) : "r"(hv), "r"(th), "r"(hv));
    return r;
}
__device__ __forceinline__ uint32_t hadd2u(uint32_t a, uint32_t b) {
    uint32_t r;
    asm("add.rn.f16x2 %0, %1, %2;" : "=r"(r) : "r"(a), "r"(b));
    return r;
}
__device__ __forceinline__ uint32_t hmul2u(uint32_t a, uint32_t b) {
    uint32_t r;
    asm("mul.rn.f16x2 %0, %1, %2;" : "=r"(r) : "r"(a), "r"(b));
    return r;
}
__device__ __forceinline__ uint32_t hfma2u(uint32_t a, uint32_t b, uint32_t c) {
    uint32_t r;
    asm("fma.rn.f16x2 %0, %1, %2, %3;" : "=r"(r) : "r"(a), "r"(b), "r"(c));
    return r;
}
__device__ __forceinline__ float2 h2f2(uint32_t h) {
    __half2 hh = *reinterpret_cast<__half2 *>(&h);
    return __half22float2(hh);
}
__device__ __forceinline__ void red2(float *p, float a, float b) {
    asm volatile("red.global.add.v2.f32 [%0], {%1,%2};" ::"l"(p), "f"(a), "f"(b)
                 : "memory");
}
__device__ __forceinline__ void red1(float *p, float a) {
    asm volatile("red.global.add.f32 [%0], %1;" ::"l"(p), "f"(a) : "memory");
}
__device__ __forceinline__ uint32_t packh(float a, float b) {
    __half2 h = __floats2half2_rn(a, b);
    return *reinterpret_cast<uint32_t *>(&h);
}
// pair-slot index for fp16x2 word w (= k/2) within a row
__device__ __forceinline__ int pslot(int w) {
    return 8 * (w >> 3) + 2 * (w & 3) + ((w >> 2) & 1);
}
__device__ __forceinline__ void mma_f16(float (&d)[4], uint32_t a0, uint32_t a1,
                                        uint32_t a2, uint32_t a3, uint32_t b0,
                                        uint32_t b1) {
    asm volatile(
        "mma.sync.aligned.m16n8k16.row.col.f32.f16.f16.f32 "
        "{%0,%1,%2,%3}, {%4,%5,%6,%7}, {%8,%9}, {%0,%1,%2,%3};\n"
        : "+f"(d[0]), "+f"(d[1]), "+f"(d[2]), "+f"(d[3])
        : "r"(a0), "r"(a1), "r"(a2), "r"(a3), "r"(b0), "r"(b1));
}

// 32 x (16*KS16) A (smem) @ B (64 cols), fp16x2 pair-slot layout
template <int SA, int SB, int KS16>
__device__ __forceinline__ void gemmH(float (&acc)[2][8][4],
                                      const uint32_t *__restrict__ A,
                                      const uint32_t *__restrict__ B, int g,
                                      int q) {
#pragma unroll
    for (int ks = 0; ks < KS16; ks++) {
        uint2 bf[8];
#pragma unroll
        for (int n = 0; n < 8; n++)
            bf[n] = *(const uint2 *)(B + (8 * n + g) * SB + 8 * ks + 2 * q);
#pragma unroll
        for (int m = 0; m < 2; m++) {
            const uint32_t *ap = A + (16 * m + g) * SA + 8 * ks + 2 * q;
            uint2 lo = *(const uint2 *)ap;
            uint2 hi = *(const uint2 *)(ap + 8 * SA);
#pragma unroll
            for (int n = 0; n < 8; n++)
                mma_f16(acc[m][n], lo.x, hi.x, lo.y, hi.y, bf[n].x, bf[n].y);
        }
    }
}
// A from registers (C-fragment reuse): Ar[m][n][0]=rows-lo pack, [1]=rows-hi
template <int SB>
__device__ __forceinline__ void gemmR(float (&acc)[2][8][4],
                                      const uint32_t (&Ar)[2][8][2],
                                      const uint32_t *__restrict__ B, int g,
                                      int q) {
#pragma unroll
    for (int ks = 0; ks < 4; ks++) {
        uint2 bf[8];
#pragma unroll
        for (int n = 0; n < 8; n++)
            bf[n] = *(const uint2 *)(B + (8 * n + g) * SB + 8 * ks + 2 * q);
#pragma unroll
        for (int m = 0; m < 2; m++) {
#pragma unroll
            for (int n = 0; n < 8; n++)
                mma_f16(acc[m][n], Ar[m][2 * ks][0], Ar[m][2 * ks][1],
                        Ar[m][2 * ks + 1][0], Ar[m][2 * ks + 1][1], bf[n].x,
                        bf[n].y);
        }
    }
}
__device__ __forceinline__ void zacc(float (&acc)[2][8][4]) {
#pragma unroll
    for (int m = 0; m < 2; m++)
#pragma unroll
        for (int n = 0; n < 8; n++)
#pragma unroll
            for (int v = 0; v < 4; v++) acc[m][n][v] = 0.f;
}
__device__ __forceinline__ void cp_s(float *dst, const float *__restrict__ src,
                                     int nfloats, int tid, int nthr) {
    const float4 *s4 = (const float4 *)src;
    float4 *d4 = (float4 *)dst;
    for (int k = tid; k < (nfloats >> 2); k += nthr) d4[k] = s4[k];
}
// stage K x 64 row-major fp32 weights into fp16x2 pair-slot [64][stride]
__device__ __forceinline__ void stage_w16(uint32_t *dst, const float *__restrict__ W,
                                          int kwords, int stride, int tid,
                                          int nthr) {
    for (int idx = tid; idx < 64 * kwords; idx += nthr) {
        int n = idx / kwords, w = idx % kwords;
        dst[n * stride + pslot(w)] =
            packh(W[(2 * w) * 64 + n], W[(2 * w + 1) * 64 + n]);
    }
}

// ---------------- time-embedding mean ----------------
__global__ void tmean_kernel(const float *__restrict__ t,
                             const float *__restrict__ w1,
                             const float *__restrict__ b1,
                             const float *__restrict__ w2,
                             const float *__restrict__ b2) {
    __shared__ float sS[16 * 64];
    int j = threadIdx.x;
    float w1j = w1[j], b1j = b1[j];
    for (int b = 0; b < 16; b++) sS[b * 64 + j] = silux(t[b] * w1j + b1j);
    __syncthreads();
    float accm = 0.f;
    for (int b = 0; b < 16; b++) {
        float s = b2[j];
        for (int k = 0; k < 64; k++) s += sS[b * 64 + k] * w2[k * 64 + j];
        accm += s;
    }
    ((float *)g_tmean4)[j] = accm * (1.0f / 16.0f);
}

// ---------------- init ----------------
__global__ void init_kernel(const float *__restrict__ x, const int *__restrict__ z,
                            const float *__restrict__ emb, float *__restrict__ out) {
    int tid = blockIdx.x * blockDim.x + threadIdx.x;
    int stride = gridDim.x * blockDim.x;
    const float4 *emb4 = (const float4 *)emb;
    for (int idx = tid; idx < NN * 16; idx += stride) {
        int i = idx >> 4, qq = idx & 15;
        float4 e = emb4[z[i] * 16 + qq];
        float4 tm = g_tmean4[qq];
        float4 r;
        r.x = e.x + tm.x; r.y = e.y + tm.y; r.z = e.z + tm.z; r.w = e.w + tm.w;
        g_h4[idx] = r;
        g_agg4[idx] = make_float4(0.f, 0.f, 0.f, 0.f);
    }
    for (int idx = tid; idx < NN * 3; idx += stride) {
        out[idx] = x[idx];
        g_dx[idx] = 0.f;
    }
    for (int i = tid; i < NN; i += stride) {
        g_x4[i] = make_float4(x[3 * i], x[3 * i + 1], x[3 * i + 2], 0.f);
    }
}

// ---------------- pre0: a,b for layer 0 (fp16 tensor core) ----------------
#define PR_AT 0
#define PR_BT 2560
#define PR_EB1 5120
#define PR_WARP 5184
#define PR_WARP_WORDS 1280
#define PRE_SMEM_BYTES ((PR_WARP + 8 * PR_WARP_WORDS) * 4)

__global__ void __launch_bounds__(256, 2)
pre0_kernel(const float *__restrict__ W1, const float *__restrict__ B1) {
    extern __shared__ float sm[];
    uint32_t *smu = (uint32_t *)sm;
    int tid = threadIdx.x;
    stage_w16(smu + PR_AT, W1, 32, 40, tid, 256);
    stage_w16(smu + PR_BT, W1 + 64 * 64, 32, 40, tid, 256);
    cp_s(sm + PR_EB1, B1, 64, tid, 256);
    __syncthreads();

    const int lane = tid & 31, wid = tid >> 5;
    const int g = lane >> 2, q = lane & 3;
    uint32_t *buf = smu + PR_WARP + wid * PR_WARP_WORDS;
    const float *gh = (const float *)g_h4;
    const int sl = pslot(lane);

    int gwarp = blockIdx.x * 8 + wid;
    int nwarps = gridDim.x * 8;
    for (int i0 = gwarp * 32; i0 < NN; i0 += nwarps * 32) {
#pragma unroll
        for (int t = 0; t < 32; t++) {
            float2 hv = *(const float2 *)(gh + (size_t)(i0 + t) * HH + 2 * lane);
            buf[t * 40 + sl] = packh(hv.x, hv.y);
        }
        __syncwarp();
        float acc[2][8][4];
        zacc(acc);
        gemmH<40, 40, 4>(acc, buf, smu + PR_AT, g, q);
#pragma unroll
        for (int m = 0; m < 2; m++) {
            int r0 = 16 * m + g, r1 = r0 + 8;
#pragma unroll
            for (int n = 0; n < 8; n++) {
                int w = 4 * n + q;
                float2 bb = *(const float2 *)(sm + PR_EB1 + 2 * w);
                g_ah[(size_t)(i0 + r0) * 32 + w] =
                    __floats2half2_rn(acc[m][n][0] + bb.x, acc[m][n][1] + bb.y);
                g_ah[(size_t)(i0 + r1) * 32 + w] =
                    __floats2half2_rn(acc[m][n][2] + bb.x, acc[m][n][3] + bb.y);
            }
        }
        zacc(acc);
        gemmH<40, 40, 4>(acc, buf, smu + PR_BT, g, q);
#pragma unroll
        for (int m = 0; m < 2; m++) {
            int r0 = 16 * m + g, r1 = r0 + 8;
#pragma unroll
            for (int n = 0; n < 8; n++) {
                int w = 4 * n + q;
                g_bh[(size_t)(i0 + r0) * 32 + w] =
                    __floats2half2_rn(acc[m][n][0], acc[m][n][1]);
                g_bh[(size_t)(i0 + r1) * 32 + w] =
                    __floats2half2_rn(acc[m][n][2], acc[m][n][3]);
            }
        }
        __syncwarp();
    }
}

// ---------------- edge kernel (fp16 TC, h2 silu, smem meta) ----------------
#define E_W2T 0
#define E_C1T 2560
#define E_B2H 5120
#define E_CB1H 5152
#define E_C2H 5184
#define E_W129H 5216
#define E_CB2 5248
#define E_WARP 5252
#define E_WARP_WORDS 1440   /* m1s 1280 + cwbuf 32 + meta 128 */
#define EDGE_SMEM_BYTES ((E_WARP + 8 * E_WARP_WORDS) * 4)

__global__ void __launch_bounds__(256, 2)
edge_kernel(const int *__restrict__ ei, const float *__restrict__ W1,
            const float *__restrict__ W2, const float *__restrict__ B2,
            const float *__restrict__ C1, const float *__restrict__ Cb1,
            const float *__restrict__ C2, const float *__restrict__ Cb2) {
    extern __shared__ float sm[];
    uint32_t *smu = (uint32_t *)sm;
    int tid = threadIdx.x;

    stage_w16(smu + E_W2T, W2, 32, 40, tid, 256);
    stage_w16(smu + E_C1T, C1, 32, 40, tid, 256);
    if (tid < 32) {
        smu[E_B2H + tid] = packh(B2[2 * tid], B2[2 * tid + 1]);
        smu[E_CB1H + tid] = packh(Cb1[2 * tid], Cb1[2 * tid + 1]);
        smu[E_C2H + tid] = packh(C2[2 * tid], C2[2 * tid + 1]);
        smu[E_W129H + tid] = packh(W1[8192 + 2 * tid], W1[8192 + 2 * tid + 1]);
    }
    if (tid == 0) sm[E_CB2] = Cb2[0];
    __syncthreads();

    const int lane = tid & 31;
    const int wid = tid >> 5;
    const int g = lane >> 2;
    const int q = lane & 3;
    uint32_t *wbase = smu + E_WARP + wid * E_WARP_WORDS;
    uint32_t *m1s = wbase;
    float *cwbuf = (float *)(wbase + 1280);
    int *meta = (int *)(wbase + 1312);
    const int sl = pslot(lane);

    float *gagg = (float *)g_agg4;
    const uint32_t *gau = (const uint32_t *)g_ah;
    const uint32_t *gbu = (const uint32_t *)g_bh;

    const uint32_t w129h = smu[E_W129H + lane];
    const float cb2v = sm[E_CB2];

    int gwarp = blockIdx.x * 8 + wid;
    int nwarps = gridDim.x * 8;

    for (int eb = gwarp * 32; eb < NE; eb += nwarps * 32) {
        int e = eb + lane;
        int s = ei[e];
        int d = ei[NE + e];
        float4 xd = g_x4[d];
        float4 xs = g_x4[s];
        float ax = xd.x - xs.x;
        float ay = xd.y - xs.y;
        float az = xd.z - xs.z;
        float d2 = ax * ax + ay * ay + az * az;
        // meta: {s, d, d2 dup-packed h2, pad}
        int4 mv;
        mv.x = s;
        mv.y = d;
        mv.z = (int)packh(d2, d2);
        mv.w = 0;
        *(int4 *)(meta + 4 * lane) = mv;
        __syncwarp();

        // phase 1: m1 = silu_h2(a[d] + b[s] + d2*w129)
#pragma unroll
        for (int t = 0; t < 32; t++) {
            int4 md = *(const int4 *)(meta + 4 * t);
            uint32_t av = gau[(size_t)md.y * 32 + lane];
            uint32_t bv = gbu[(size_t)md.x * 32 + lane];
            uint32_t ef = hfma2u((uint32_t)md.z, w129h, hadd2u(av, bv));
            m1s[t * 40 + sl] = silu_h2(ef);
        }
        __syncwarp();

        // GEMM2: m = silu_h2(m1 @ W2 + b2)
        float acc[2][8][4];
        zacc(acc);
        gemmH<40, 40, 4>(acc, m1s, smu + E_W2T, g, q);

        // epilogue: h2 silu, red2 agg scatter (fp32), mreg = silu output
        uint32_t mreg[2][8][2];
#pragma unroll
        for (int m = 0; m < 2; m++) {
            int r0 = 16 * m + g;
            int r1 = r0 + 8;
            int d0 = meta[4 * r0 + 1];
            int d1 = meta[4 * r1 + 1];
            float *agg0 = gagg + (size_t)d0 * HH;
            float *agg1 = gagg + (size_t)d1 * HH;
#pragma unroll
            for (int n = 0; n < 8; n++) {
                int c0 = 8 * n + 2 * q;
                uint32_t b2h = smu[E_B2H + 4 * n + q];
                uint32_t v0 = silu_h2(
                    hadd2u(packh(acc[m][n][0], acc[m][n][1]), b2h));
                uint32_t v1 = silu_h2(
                    hadd2u(packh(acc[m][n][2], acc[m][n][3]), b2h));
                float2 f0 = h2f2(v0);
                float2 f1 = h2f2(v1);
                red2(agg0 + c0, f0.x, f0.y);
                red2(agg1 + c0, f1.x, f1.y);
                mreg[m][n][0] = v0;
                mreg[m][n][1] = v1;
            }
        }

        // coord MLP: cw = silu(m @ C1 + cb1) @ C2 + cb2 (A from registers)
        zacc(acc);
        gemmR<40>(acc, mreg, smu + E_C1T, g, q);

        float cwp[2][2] = {{0.f, 0.f}, {0.f, 0.f}};
#pragma unroll
        for (int m = 0; m < 2; m++)
#pragma unroll
            for (int n = 0; n < 8; n++) {
                uint32_t cb1h = smu[E_CB1H + 4 * n + q];
                uint32_t c2h = smu[E_C2H + 4 * n + q];
                uint32_t p0 = hmul2u(
                    silu_h2(hadd2u(packh(acc[m][n][0], acc[m][n][1]), cb1h)),
                    c2h);
                uint32_t p1 = hmul2u(
                    silu_h2(hadd2u(packh(acc[m][n][2], acc[m][n][3]), cb1h)),
                    c2h);
                float2 f0 = h2f2(p0);
                float2 f1 = h2f2(p1);
                cwp[m][0] += f0.x + f0.y;
                cwp[m][1] += f1.x + f1.y;
            }
#pragma unroll
        for (int ofs = 1; ofs <= 2; ofs <<= 1) {
#pragma unroll
            for (int m = 0; m < 2; m++) {
                cwp[m][0] += __shfl_xor_sync(0xffffffffu, cwp[m][0], ofs);
                cwp[m][1] += __shfl_xor_sync(0xffffffffu, cwp[m][1], ofs);
            }
        }
        if (q == 0) {
#pragma unroll
            for (int m = 0; m < 2; m++) {
                cwbuf[16 * m + g] = cwp[m][0] + cb2v;
                cwbuf[16 * m + g + 8] = cwp[m][1] + cb2v;
            }
        }
        __syncwarp();

        float cw = cwbuf[lane];
        red1(&g_dx[3 * d + 0], ax * cw);
        red1(&g_dx[3 * d + 1], ay * cw);
        red1(&g_dx[3 * d + 2], az * cw);
        __syncwarp();
    }
}

// ---------------- node kernel (fp16 TC, split-K, h2 silu, 2 CTA/SM) --------
#define ND_W1A 0
#define ND_W1B 2560
#define ND_W2T 5120
#define ND_AT 7680
#define ND_BT 10240
#define ND_NB1H 12800
#define ND_NB2 12832
#define ND_EB1H 12896
#define ND_WARP 12928
#define ND_WARP_WORDS 1280
#define NODE_SMEM_BYTES ((ND_WARP + 8 * ND_WARP_WORDS) * 4)

__global__ void __launch_bounds__(256, 2)
node_kernel(float *__restrict__ xout, const float *__restrict__ NW1,
            const float *__restrict__ NB1, const float *__restrict__ NW2,
            const float *__restrict__ NB2, const float *__restrict__ EW1n,
            const float *__restrict__ EB1n, int do_pre) {
    extern __shared__ float sm[];
    uint32_t *smu = (uint32_t *)sm;
    int tid = threadIdx.x;

    stage_w16(smu + ND_W1A, NW1, 32, 40, tid, 256);           // nf rows 0..63 (h)
    stage_w16(smu + ND_W1B, NW1 + 64 * 64, 32, 40, tid, 256); // rows 64..127 (agg)
    stage_w16(smu + ND_W2T, NW2, 32, 40, tid, 256);
    if (do_pre) {
        stage_w16(smu + ND_AT, EW1n, 32, 40, tid, 256);
        stage_w16(smu + ND_BT, EW1n + 64 * 64, 32, 40, tid, 256);
    }
    if (tid < 32) {
        smu[ND_NB1H + tid] = packh(NB1[2 * tid], NB1[2 * tid + 1]);
        if (do_pre)
            smu[ND_EB1H + tid] = packh(EB1n[2 * tid], EB1n[2 * tid + 1]);
    }
    cp_s(sm + ND_NB2, NB2, 64, tid, 256);
    __syncthreads();

    const int lane = tid & 31, wid = tid >> 5;
    const int g = lane >> 2, q = lane & 3;
    uint32_t *buf = smu + ND_WARP + wid * ND_WARP_WORDS;
    const int sl = pslot(lane);

    float *gh = (float *)g_h4;
    float *gagg = (float *)g_agg4;
    uint32_t *gau = (uint32_t *)g_ah;
    uint32_t *gbu = (uint32_t *)g_bh;

    int gwarp = blockIdx.x * 8 + wid;
    int nwarps = gridDim.x * 8;

    for (int i0 = gwarp * 32; i0 < NN; i0 += nwarps * 32) {
        // stage h fp16 (stride 40)
#pragma unroll
        for (int t = 0; t < 32; t++) {
            float2 hv = *(const float2 *)(gh + (size_t)(i0 + t) * HH + 2 * lane);
            buf[t * 40 + sl] = packh(hv.x, hv.y);
        }
        __syncwarp();

        float acc[2][8][4];
        zacc(acc);
        gemmH<40, 40, 4>(acc, buf, smu + ND_W1A, g, q);
        __syncwarp();

        // stage agg fp16 (overwrite h staging); zero agg
#pragma unroll
        for (int t = 0; t < 32; t++) {
            size_t ro = (size_t)(i0 + t) * HH;
            float2 av = *(const float2 *)(gagg + ro + 2 * lane);
            *(float2 *)(gagg + ro + 2 * lane) = make_float2(0.f, 0.f);
            buf[t * 40 + sl] = packh(av.x, av.y);
        }
        __syncwarp();
        gemmH<40, 40, 4>(acc, buf, smu + ND_W1B, g, q);  // accumulate
        __syncwarp();

        // m1 = silu_h2(acc + nb1) -> A-fragments in registers
        uint32_t mreg[2][8][2];
#pragma unroll
        for (int m = 0; m < 2; m++) {
#pragma unroll
            for (int n = 0; n < 8; n++) {
                uint32_t nb = smu[ND_NB1H + 4 * n + q];
                mreg[m][n][0] = silu_h2(
                    hadd2u(packh(acc[m][n][0], acc[m][n][1]), nb));
                mreg[m][n][1] = silu_h2(
                    hadd2u(packh(acc[m][n][2], acc[m][n][3]), nb));
            }
        }

        zacc(acc);
        gemmR<40>(acc, mreg, smu + ND_W2T, g, q);

        // hnew = h_old + acc + nb2 -> global; pack hnew for pre gemms
#pragma unroll
        for (int m = 0; m < 2; m++) {
            int r0 = 16 * m + g, r1 = r0 + 8;
            float *h0 = gh + (size_t)(i0 + r0) * HH;
            float *h1 = gh + (size_t)(i0 + r1) * HH;
#pragma unroll
            for (int n = 0; n < 8; n++) {
                int c0 = 8 * n + 2 * q;
                float2 bb = *(const float2 *)(sm + ND_NB2 + c0);
                float2 o0 = *(const float2 *)(h0 + c0);
                float2 o1 = *(const float2 *)(h1 + c0);
                o0.x += acc[m][n][0] + bb.x;
                o0.y += acc[m][n][1] + bb.y;
                o1.x += acc[m][n][2] + bb.x;
                o1.y += acc[m][n][3] + bb.y;
                *(float2 *)(h0 + c0) = o0;
                *(float2 *)(h1 + c0) = o1;
                if (do_pre) {
                    mreg[m][n][0] = packh(o0.x, o0.y);
                    mreg[m][n][1] = packh(o1.x, o1.y);
                }
            }
        }

        if (do_pre) {
            zacc(acc);
            gemmR<40>(acc, mreg, smu + ND_AT, g, q);
#pragma unroll
            for (int m = 0; m < 2; m++) {
                int r0 = 16 * m + g, r1 = r0 + 8;
#pragma unroll
                for (int n = 0; n < 8; n++) {
                    int w = 4 * n + q;
                    uint32_t eb = smu[ND_EB1H + w];
                    gau[(size_t)(i0 + r0) * 32 + w] =
                        hadd2u(packh(acc[m][n][0], acc[m][n][1]), eb);
                    gau[(size_t)(i0 + r1) * 32 + w] =
                        hadd2u(packh(acc[m][n][2], acc[m][n][3]), eb);
                }
            }
            zacc(acc);
            gemmR<40>(acc, mreg, smu + ND_BT, g, q);
#pragma unroll
            for (int m = 0; m < 2; m++) {
                int r0 = 16 * m + g, r1 = r0 + 8;
#pragma unroll
                for (int n = 0; n < 8; n++) {
                    int w = 4 * n + q;
                    gbu[(size_t)(i0 + r0) * 32 + w] =
                        packh(acc[m][n][0], acc[m][n][1]);
                    gbu[(size_t)(i0 + r1) * 32 + w] =
                        packh(acc[m][n][2], acc[m][n][3]);
                }
            }
        }

        // x += dx; update padded coords; reset dx (lane = node)
        int i = i0 + lane;
        float4 xv = g_x4[i];
        xv.x += g_dx[3 * i + 0];
        xv.y += g_dx[3 * i + 1];
        xv.z += g_dx[3 * i + 2];
        g_x4[i] = xv;
        xout[3 * i + 0] = xv.x;
        xout[3 * i + 1] = xv.y;
        xout[3 * i + 2] = xv.z;
        g_dx[3 * i + 0] = 0.f;
        g_dx[3 * i + 1] = 0.f;
        g_dx[3 * i + 2] = 0.f;
        __syncwarp();
    }
}

// ---------------- launch ----------------
extern "C" void kernel_launch(void *const *d_in, const int *in_sizes, int n_in,
                              void *d_out, int out_size) {
    const float *x   = (const float *)d_in[0];
    const int   *z   = (const int *)d_in[1];
    const float *t   = (const float *)d_in[2];
    const int   *ei  = (const int *)d_in[3];
    const float *emb = (const float *)d_in[4];
    const float *tw1 = (const float *)d_in[5];
    const float *tb1 = (const float *)d_in[6];
    const float *tw2 = (const float *)d_in[7];
    const float *tb2 = (const float *)d_in[8];
    const float *ew1 = (const float *)d_in[9];
    const float *eb1 = (const float *)d_in[10];
    const float *ew2 = (const float *)d_in[11];
    const float *eb2 = (const float *)d_in[12];
    const float *cw1 = (const float *)d_in[13];
    const float *cb1 = (const float *)d_in[14];
    const float *cw2 = (const float *)d_in[15];
    const float *cb2 = (const float *)d_in[16];
    const float *nw1 = (const float *)d_in[17];
    const float *nb1 = (const float *)d_in[18];
    const float *nw2 = (const float *)d_in[19];
    const float *nb2 = (const float *)d_in[20];
    float *out = (float *)d_out;

    cudaFuncSetAttribute(edge_kernel, cudaFuncAttributeMaxDynamicSharedMemorySize,
                         EDGE_SMEM_BYTES);
    cudaFuncSetAttribute(node_kernel, cudaFuncAttributeMaxDynamicSharedMemorySize,
                         NODE_SMEM_BYTES);
    cudaFuncSetAttribute(pre0_kernel, cudaFuncAttributeMaxDynamicSharedMemorySize,
                         PRE_SMEM_BYTES);

    tmean_kernel<<<1, 64>>>(t, tw1, tb1, tw2, tb2);
    init_kernel<<<2048, 256>>>(x, z, emb, out);
    pre0_kernel<<<296, 256, PRE_SMEM_BYTES>>>(ew1, eb1);
    for (int l = 0; l < NLAYERS; l++) {
        edge_kernel<<<296, 256, EDGE_SMEM_BYTES>>>(
            ei, ew1 + l * 8256, ew2 + l * 4096, eb2 + l * 64,
            cw1 + l * 4096, cb1 + l * 64, cw2 + l * 64, cb2 + l);
        int do_pre = (l + 1 < NLAYERS);
        node_kernel<<<296, 256, NODE_SMEM_BYTES>>>(
            out, nw1 + l * 8192, nb1 + l * 64, nw2 + l * 4096, nb2 + l * 64,
            do_pre ? (ew1 + (l + 1) * 8256) : ew1,
            do_pre ? (eb1 + (l + 1) * 64) : eb1, do_pre);
    }
    (void)in_sizes; (void)n_in; (void)out_size;
}

// round 13
// speedup vs baseline: 1.2351x; 1.2351x over previous
#include <cuda_runtime.h>
#include <cuda_fp16.h>
#include <cstdint>

#define NN 100000
#define NE 1600000
#define HH 64
#define NLAYERS 3

// ---------------- device scratch ----------------
__device__ float4 g_h4[NN * 16];     // h: (N, 64) fp32
__device__ float4 g_agg4[NN * 16];   // agg: (N, 64) fp32
__device__ __half2 g_ah[NN * 32];    // a[n] = h[n] @ W1[0:64] + e_b1 (fp16)
__device__ __half2 g_bh[NN * 32];    // b[n] = h[n] @ W1[64:128]      (fp16)
__device__ float4 g_x4[NN];          // padded coords (x,y,z,0)
__device__ float  g_dx[NN * 3];
__device__ float4 g_tmean4[16];

// ---------------- helpers ----------------
__device__ __forceinline__ float siluf(float v) {
    float th;
    float hv = 0.5f * v;
    asm("tanh.approx.f32 %0, %1;" : "=f"(th) : "f"(hv));
    return fmaf(hv, th, hv);
}
__device__ __forceinline__ float silux(float v) {
    return __fdividef(v, 1.0f + __expf(-v));
}
// packed half2 silu: silu(x) = 0.5x + 0.5x*tanh(0.5x)
__device__ __forceinline__ uint32_t silu_h2(uint32_t x) {
    uint32_t hv, th, r;
    asm("mul.rn.f16x2 %0, %1, %2;" : "=r"(hv) : "r"(x), "r"(0x38003800u));
    asm("tanh.approx.f16x2 %0, %1;" : "=r"(th) : "r"(hv));
    asm("fma.rn.f16x2 %0, %1, %2, %3;" : "=r"(r) : "r"(hv), "r"(th), "r"(hv));
    return r;
}
__device__ __forceinline__ uint32_t hadd2u(uint32_t a, uint32_t b) {
    uint32_t r;
    asm("add.rn.f16x2 %0, %1, %2;" : "=r"(r) : "r"(a), "r"(b));
    return r;
}
__device__ __forceinline__ uint32_t hmul2u(uint32_t a, uint32_t b) {
    uint32_t r;
    asm("mul.rn.f16x2 %0, %1, %2;" : "=r"(r) : "r"(a), "r"(b));
    return r;
}
__device__ __forceinline__ float2 h2f2(uint32_t h) {
    __half2 hh = *reinterpret_cast<__half2 *>(&h);
    return __half22float2(hh);
}
__device__ __forceinline__ void red2(float *p, float a, float b) {
    asm volatile("red.global.add.v2.f32 [%0], {%1,%2};" ::"l"(p), "f"(a), "f"(b)
                 : "memory");
}
__device__ __forceinline__ void red1(float *p, float a) {
    asm volatile("red.global.add.f32 [%0], %1;" ::"l"(p), "f"(a) : "memory");
}
__device__ __forceinline__ uint32_t packh(float a, float b) {
    __half2 h = __floats2half2_rn(a, b);
    return *reinterpret_cast<uint32_t *>(&h);
}
// pair-slot index for fp16x2 word w (= k/2) within a row
__device__ __forceinline__ int pslot(int w) {
    return 8 * (w >> 3) + 2 * (w & 3) + ((w >> 2) & 1);
}
// fp32-accum mma (node/pre path)
__device__ __forceinline__ void mma_f16(float (&d)[4], uint32_t a0, uint32_t a1,
                                        uint32_t a2, uint32_t a3, uint32_t b0,
                                        uint32_t b1) {
    asm volatile(
        "mma.sync.aligned.m16n8k16.row.col.f32.f16.f16.f32 "
        "{%0,%1,%2,%3}, {%4,%5,%6,%7}, {%8,%9}, {%0,%1,%2,%3};\n"
        : "+f"(d[0]), "+f"(d[1]), "+f"(d[2]), "+f"(d[3])
        : "r"(a0), "r"(a1), "r"(a2), "r"(a3), "r"(b0), "r"(b1));
}
// f16-accum mma (edge path): D fragment {d0,d1} = packed h2 pairs
__device__ __forceinline__ void mma_f16d(uint32_t (&d)[2], uint32_t a0,
                                         uint32_t a1, uint32_t a2, uint32_t a3,
                                         uint32_t b0, uint32_t b1) {
    asm volatile(
        "mma.sync.aligned.m16n8k16.row.col.f16.f16.f16.f16 "
        "{%0,%1}, {%2,%3,%4,%5}, {%6,%7}, {%0,%1};\n"
        : "+r"(d[0]), "+r"(d[1])
        : "r"(a0), "r"(a1), "r"(a2), "r"(a3), "r"(b0), "r"(b1));
}

// ---- fp32-acc gemms (node/pre) ----
template <int SA, int SB, int KS16>
__device__ __forceinline__ void gemmH(float (&acc)[2][8][4],
                                      const uint32_t *__restrict__ A,
                                      const uint32_t *__restrict__ B, int g,
                                      int q) {
#pragma unroll
    for (int ks = 0; ks < KS16; ks++) {
        uint2 bf[8];
#pragma unroll
        for (int n = 0; n < 8; n++)
            bf[n] = *(const uint2 *)(B + (8 * n + g) * SB + 8 * ks + 2 * q);
#pragma unroll
        for (int m = 0; m < 2; m++) {
            const uint32_t *ap = A + (16 * m + g) * SA + 8 * ks + 2 * q;
            uint2 lo = *(const uint2 *)ap;
            uint2 hi = *(const uint2 *)(ap + 8 * SA);
#pragma unroll
            for (int n = 0; n < 8; n++)
                mma_f16(acc[m][n], lo.x, hi.x, lo.y, hi.y, bf[n].x, bf[n].y);
        }
    }
}
template <int SB>
__device__ __forceinline__ void gemmR(float (&acc)[2][8][4],
                                      const uint32_t (&Ar)[2][8][2],
                                      const uint32_t *__restrict__ B, int g,
                                      int q) {
#pragma unroll
    for (int ks = 0; ks < 4; ks++) {
        uint2 bf[8];
#pragma unroll
        for (int n = 0; n < 8; n++)
            bf[n] = *(const uint2 *)(B + (8 * n + g) * SB + 8 * ks + 2 * q);
#pragma unroll
        for (int m = 0; m < 2; m++) {
#pragma unroll
            for (int n = 0; n < 8; n++)
                mma_f16(acc[m][n], Ar[m][2 * ks][0], Ar[m][2 * ks][1],
                        Ar[m][2 * ks + 1][0], Ar[m][2 * ks + 1][1], bf[n].x,
                        bf[n].y);
        }
    }
}
// ---- f16-acc gemms (edge) ----
template <int SA, int SB, int KS16>
__device__ __forceinline__ void gemmH16(uint32_t (&acc)[2][8][2],
                                        const uint32_t *__restrict__ A,
                                        const uint32_t *__restrict__ B, int g,
                                        int q) {
#pragma unroll
    for (int ks = 0; ks < KS16; ks++) {
        uint2 bf[8];
#pragma unroll
        for (int n = 0; n < 8; n++)
            bf[n] = *(const uint2 *)(B + (8 * n + g) * SB + 8 * ks + 2 * q);
#pragma unroll
        for (int m = 0; m < 2; m++) {
            const uint32_t *ap = A + (16 * m + g) * SA + 8 * ks + 2 * q;
            uint2 lo = *(const uint2 *)ap;
            uint2 hi = *(const uint2 *)(ap + 8 * SA);
#pragma unroll
            for (int n = 0; n < 8; n++)
                mma_f16d(acc[m][n], lo.x, hi.x, lo.y, hi.y, bf[n].x, bf[n].y);
        }
    }
}
template <int SB>
__device__ __forceinline__ void gemmR16(uint32_t (&acc)[2][8][2],
                                        const uint32_t (&Ar)[2][8][2],
                                        const uint32_t *__restrict__ B, int g,
                                        int q) {
#pragma unroll
    for (int ks = 0; ks < 4; ks++) {
        uint2 bf[8];
#pragma unroll
        for (int n = 0; n < 8; n++)
            bf[n] = *(const uint2 *)(B + (8 * n + g) * SB + 8 * ks + 2 * q);
#pragma unroll
        for (int m = 0; m < 2; m++) {
#pragma unroll
            for (int n = 0; n < 8; n++)
                mma_f16d(acc[m][n], Ar[m][2 * ks][0], Ar[m][2 * ks][1],
                         Ar[m][2 * ks + 1][0], Ar[m][2 * ks + 1][1], bf[n].x,
                         bf[n].y);
        }
    }
}
__device__ __forceinline__ void zacc(float (&acc)[2][8][4]) {
#pragma unroll
    for (int m = 0; m < 2; m++)
#pragma unroll
        for (int n = 0; n < 8; n++)
#pragma unroll
            for (int v = 0; v < 4; v++) acc[m][n][v] = 0.f;
}
__device__ __forceinline__ void zacc16(uint32_t (&acc)[2][8][2]) {
#pragma unroll
    for (int m = 0; m < 2; m++)
#pragma unroll
        for (int n = 0; n < 8; n++) {
            acc[m][n][0] = 0u;
            acc[m][n][1] = 0u;
        }
}
__device__ __forceinline__ void cp_s(float *dst, const float *__restrict__ src,
                                     int nfloats, int tid, int nthr) {
    const float4 *s4 = (const float4 *)src;
    float4 *d4 = (float4 *)dst;
    for (int k = tid; k < (nfloats >> 2); k += nthr) d4[k] = s4[k];
}
// stage K x 64 row-major fp32 weights into fp16x2 pair-slot [64][stride]
__device__ __forceinline__ void stage_w16(uint32_t *dst, const float *__restrict__ W,
                                          int kwords, int stride, int tid,
                                          int nthr) {
    for (int idx = tid; idx < 64 * kwords; idx += nthr) {
        int n = idx / kwords, w = idx % kwords;
        dst[n * stride + pslot(w)] =
            packh(W[(2 * w) * 64 + n], W[(2 * w + 1) * 64 + n]);
    }
}

// ---------------- time-embedding mean ----------------
__global__ void tmean_kernel(const float *__restrict__ t,
                             const float *__restrict__ w1,
                             const float *__restrict__ b1,
                             const float *__restrict__ w2,
                             const float *__restrict__ b2) {
    __shared__ float sS[16 * 64];
    int j = threadIdx.x;
    float w1j = w1[j], b1j = b1[j];
    for (int b = 0; b < 16; b++) sS[b * 64 + j] = silux(t[b] * w1j + b1j);
    __syncthreads();
    float accm = 0.f;
    for (int b = 0; b < 16; b++) {
        float s = b2[j];
        for (int k = 0; k < 64; k++) s += sS[b * 64 + k] * w2[k * 64 + j];
        accm += s;
    }
    ((float *)g_tmean4)[j] = accm * (1.0f / 16.0f);
}

// ---------------- init ----------------
__global__ void init_kernel(const float *__restrict__ x, const int *__restrict__ z,
                            const float *__restrict__ emb, float *__restrict__ out) {
    int tid = blockIdx.x * blockDim.x + threadIdx.x;
    int stride = gridDim.x * blockDim.x;
    const float4 *emb4 = (const float4 *)emb;
    for (int idx = tid; idx < NN * 16; idx += stride) {
        int i = idx >> 4, qq = idx & 15;
        float4 e = emb4[z[i] * 16 + qq];
        float4 tm = g_tmean4[qq];
        float4 r;
        r.x = e.x + tm.x; r.y = e.y + tm.y; r.z = e.z + tm.z; r.w = e.w + tm.w;
        g_h4[idx] = r;
        g_agg4[idx] = make_float4(0.f, 0.f, 0.f, 0.f);
    }
    for (int idx = tid; idx < NN * 3; idx += stride) {
        out[idx] = x[idx];
        g_dx[idx] = 0.f;
    }
    for (int i = tid; i < NN; i += stride) {
        g_x4[i] = make_float4(x[3 * i], x[3 * i + 1], x[3 * i + 2], 0.f);
    }
}

// ---------------- pre0: a,b for layer 0 (fp16 tensor core) ----------------
#define PR_AT 0
#define PR_BT 2560
#define PR_EB1 5120
#define PR_WARP 5184
#define PR_WARP_WORDS 1280
#define PRE_SMEM_BYTES ((PR_WARP + 8 * PR_WARP_WORDS) * 4)

__global__ void __launch_bounds__(256, 2)
pre0_kernel(const float *__restrict__ W1, const float *__restrict__ B1) {
    extern __shared__ float sm[];
    uint32_t *smu = (uint32_t *)sm;
    int tid = threadIdx.x;
    stage_w16(smu + PR_AT, W1, 32, 40, tid, 256);
    stage_w16(smu + PR_BT, W1 + 64 * 64, 32, 40, tid, 256);
    cp_s(sm + PR_EB1, B1, 64, tid, 256);
    __syncthreads();

    const int lane = tid & 31, wid = tid >> 5;
    const int g = lane >> 2, q = lane & 3;
    uint32_t *buf = smu + PR_WARP + wid * PR_WARP_WORDS;
    const float *gh = (const float *)g_h4;
    const int sl = pslot(lane);

    int gwarp = blockIdx.x * 8 + wid;
    int nwarps = gridDim.x * 8;
    for (int i0 = gwarp * 32; i0 < NN; i0 += nwarps * 32) {
#pragma unroll
        for (int t = 0; t < 32; t++) {
            float2 hv = *(const float2 *)(gh + (size_t)(i0 + t) * HH + 2 * lane);
            buf[t * 40 + sl] = packh(hv.x, hv.y);
        }
        __syncwarp();
        float acc[2][8][4];
        zacc(acc);
        gemmH<40, 40, 4>(acc, buf, smu + PR_AT, g, q);
#pragma unroll
        for (int m = 0; m < 2; m++) {
            int r0 = 16 * m + g, r1 = r0 + 8;
#pragma unroll
            for (int n = 0; n < 8; n++) {
                int w = 4 * n + q;
                float2 bb = *(const float2 *)(sm + PR_EB1 + 2 * w);
                g_ah[(size_t)(i0 + r0) * 32 + w] =
                    __floats2half2_rn(acc[m][n][0] + bb.x, acc[m][n][1] + bb.y);
                g_ah[(size_t)(i0 + r1) * 32 + w] =
                    __floats2half2_rn(acc[m][n][2] + bb.x, acc[m][n][3] + bb.y);
            }
        }
        zacc(acc);
        gemmH<40, 40, 4>(acc, buf, smu + PR_BT, g, q);
#pragma unroll
        for (int m = 0; m < 2; m++) {
            int r0 = 16 * m + g, r1 = r0 + 8;
#pragma unroll
            for (int n = 0; n < 8; n++) {
                int w = 4 * n + q;
                g_bh[(size_t)(i0 + r0) * 32 + w] =
                    __floats2half2_rn(acc[m][n][0], acc[m][n][1]);
                g_bh[(size_t)(i0 + r1) * 32 + w] =
                    __floats2half2_rn(acc[m][n][2], acc[m][n][3]);
            }
        }
        __syncwarp();
    }
}

// ---------------- edge kernel (f16-accum TC, 3 CTA/SM) ----------------
#define E_W2T 0
#define E_C1T 2560
#define E_B2H 5120
#define E_CB1H 5152
#define E_C2H 5184
#define E_W129 5216
#define E_CB2 5280
#define E_WARP 5284
#define E_WARP_WORDS 1312   /* m1s 1280 + cwbuf 32 */
#define EDGE_SMEM_BYTES ((E_WARP + 8 * E_WARP_WORDS) * 4)

__global__ void __launch_bounds__(256, 3)
edge_kernel(const int *__restrict__ ei, const float *__restrict__ W1,
            const float *__restrict__ W2, const float *__restrict__ B2,
            const float *__restrict__ C1, const float *__restrict__ Cb1,
            const float *__restrict__ C2, const float *__restrict__ Cb2) {
    extern __shared__ float sm[];
    uint32_t *smu = (uint32_t *)sm;
    int tid = threadIdx.x;

    stage_w16(smu + E_W2T, W2, 32, 40, tid, 256);
    stage_w16(smu + E_C1T, C1, 32, 40, tid, 256);
    if (tid < 32) {
        smu[E_B2H + tid] = packh(B2[2 * tid], B2[2 * tid + 1]);
        smu[E_CB1H + tid] = packh(Cb1[2 * tid], Cb1[2 * tid + 1]);
        smu[E_C2H + tid] = packh(C2[2 * tid], C2[2 * tid + 1]);
    }
    cp_s(sm + E_W129, W1 + 8192, 64, tid, 256);
    if (tid == 0) sm[E_CB2] = Cb2[0];
    __syncthreads();

    const int lane = tid & 31;
    const int wid = tid >> 5;
    const int g = lane >> 2;
    const int q = lane & 3;
    uint32_t *m1s = smu + E_WARP + wid * E_WARP_WORDS;
    float *cwbuf = sm + E_WARP + wid * E_WARP_WORDS + 1280;
    const int sl = pslot(lane);

    float *gagg = (float *)g_agg4;
    const uint32_t *gau = (const uint32_t *)g_ah;
    const uint32_t *gbu = (const uint32_t *)g_bh;

    const float w129x = sm[E_W129 + 2 * lane];
    const float w129y = sm[E_W129 + 2 * lane + 1];
    const float cb2v = sm[E_CB2];

    int gwarp = blockIdx.x * 8 + wid;
    int nwarps = gridDim.x * 8;

    for (int eb = gwarp * 32; eb < NE; eb += nwarps * 32) {
        int e = eb + lane;
        int s = ei[e];
        int d = ei[NE + e];
        float4 xd = g_x4[d];
        float4 xs = g_x4[s];
        float ax = xd.x - xs.x;
        float ay = xd.y - xs.y;
        float az = xd.z - xs.z;
        float d2 = ax * ax + ay * ay + az * az;

        // m1 = silu(a[d] + b[s] + d2*w129) -> staged fp16 pair-slot (as R11)
#pragma unroll
        for (int t = 0; t < 32; t++) {
            int dt = __shfl_sync(0xffffffffu, d, t);
            int st = __shfl_sync(0xffffffffu, s, t);
            float d2t = __shfl_sync(0xffffffffu, d2, t);
            float2 av = h2f2(gau[(size_t)dt * 32 + lane]);
            float2 bv = h2f2(gbu[(size_t)st * 32 + lane]);
            float m0 = siluf(fmaf(d2t, w129x, av.x + bv.x));
            float m1v = siluf(fmaf(d2t, w129y, av.y + bv.y));
            m1s[t * 40 + sl] = packh(m0, m1v);
        }
        __syncwarp();

        // GEMM2 (f16 acc): m = silu_h2(m1 @ W2 + b2) -- D fragment is packed
        uint32_t acc[2][8][2];
        zacc16(acc);
        gemmH16<40, 40, 4>(acc, m1s, smu + E_W2T, g, q);

        // epilogue: h2 bias+silu (no cvt), red2 agg scatter, mreg = silu out
        uint32_t mreg[2][8][2];
#pragma unroll
        for (int m = 0; m < 2; m++) {
            int r0 = 16 * m + g;
            int r1 = r0 + 8;
            int d0 = __shfl_sync(0xffffffffu, d, r0);
            int d1 = __shfl_sync(0xffffffffu, d, r1);
            float *agg0 = gagg + (size_t)d0 * HH;
            float *agg1 = gagg + (size_t)d1 * HH;
#pragma unroll
            for (int n = 0; n < 8; n++) {
                int c0 = 8 * n + 2 * q;
                uint32_t b2h = smu[E_B2H + 4 * n + q];
                uint32_t v0 = silu_h2(hadd2u(acc[m][n][0], b2h));
                uint32_t v1 = silu_h2(hadd2u(acc[m][n][1], b2h));
                float2 f0 = h2f2(v0);
                float2 f1 = h2f2(v1);
                red2(agg0 + c0, f0.x, f0.y);
                red2(agg1 + c0, f1.x, f1.y);
                mreg[m][n][0] = v0;
                mreg[m][n][1] = v1;
            }
        }

        // coord MLP (f16 acc): cw = silu(m @ C1 + cb1) @ C2 + cb2
        zacc16(acc);
        gemmR16<40>(acc, mreg, smu + E_C1T, g, q);

        float cwp[2][2] = {{0.f, 0.f}, {0.f, 0.f}};
#pragma unroll
        for (int m = 0; m < 2; m++)
#pragma unroll
            for (int n = 0; n < 8; n++) {
                uint32_t cb1h = smu[E_CB1H + 4 * n + q];
                uint32_t c2h = smu[E_C2H + 4 * n + q];
                uint32_t p0 = hmul2u(silu_h2(hadd2u(acc[m][n][0], cb1h)), c2h);
                uint32_t p1 = hmul2u(silu_h2(hadd2u(acc[m][n][1], cb1h)), c2h);
                float2 f0 = h2f2(p0);
                float2 f1 = h2f2(p1);
                cwp[m][0] += f0.x + f0.y;
                cwp[m][1] += f1.x + f1.y;
            }
#pragma unroll
        for (int ofs = 1; ofs <= 2; ofs <<= 1) {
#pragma unroll
            for (int m = 0; m < 2; m++) {
                cwp[m][0] += __shfl_xor_sync(0xffffffffu, cwp[m][0], ofs);
                cwp[m][1] += __shfl_xor_sync(0xffffffffu, cwp[m][1], ofs);
            }
        }
        if (q == 0) {
#pragma unroll
            for (int m = 0; m < 2; m++) {
                cwbuf[16 * m + g] = cwp[m][0] + cb2v;
                cwbuf[16 * m + g + 8] = cwp[m][1] + cb2v;
            }
        }
        __syncwarp();

        float cw = cwbuf[lane];
        red1(&g_dx[3 * d + 0], ax * cw);
        red1(&g_dx[3 * d + 1], ay * cw);
        red1(&g_dx[3 * d + 2], az * cw);
        __syncwarp();
    }
}

// ---------------- node kernel (fp32-acc TC, split-K, reg A-reuse) ----------
#define ND_W1A 0
#define ND_W1B 2560
#define ND_W2T 5120
#define ND_AT 7680
#define ND_BT 10240
#define ND_NB1 12800
#define ND_NB2 12864
#define ND_EB1 12928
#define ND_WARP 12992
#define ND_WARP_WORDS 1280
#define NODE_SMEM_BYTES ((ND_WARP + 8 * ND_WARP_WORDS) * 4)

__global__ void __launch_bounds__(256, 2)
node_kernel(float *__restrict__ xout, const float *__restrict__ NW1,
            const float *__restrict__ NB1, const float *__restrict__ NW2,
            const float *__restrict__ NB2, const float *__restrict__ EW1n,
            const float *__restrict__ EB1n, int do_pre) {
    extern __shared__ float sm[];
    uint32_t *smu = (uint32_t *)sm;
    int tid = threadIdx.x;

    stage_w16(smu + ND_W1A, NW1, 32, 40, tid, 256);           // nf rows 0..63 (h)
    stage_w16(smu + ND_W1B, NW1 + 64 * 64, 32, 40, tid, 256); // rows 64..127 (agg)
    stage_w16(smu + ND_W2T, NW2, 32, 40, tid, 256);
    if (do_pre) {
        stage_w16(smu + ND_AT, EW1n, 32, 40, tid, 256);
        stage_w16(smu + ND_BT, EW1n + 64 * 64, 32, 40, tid, 256);
    }
    cp_s(sm + ND_NB1, NB1, 64, tid, 256);
    cp_s(sm + ND_NB2, NB2, 64, tid, 256);
    if (do_pre) cp_s(sm + ND_EB1, EB1n, 64, tid, 256);
    __syncthreads();

    const int lane = tid & 31, wid = tid >> 5;
    const int g = lane >> 2, q = lane & 3;
    uint32_t *buf = smu + ND_WARP + wid * ND_WARP_WORDS;
    const int sl = pslot(lane);

    float *gh = (float *)g_h4;
    float *gagg = (float *)g_agg4;
    uint32_t *gau = (uint32_t *)g_ah;
    uint32_t *gbu = (uint32_t *)g_bh;

    int gwarp = blockIdx.x * 8 + wid;
    int nwarps = gridDim.x * 8;

    for (int i0 = gwarp * 32; i0 < NN; i0 += nwarps * 32) {
        // stage h fp16 (stride 40)
#pragma unroll
        for (int t = 0; t < 32; t++) {
            float2 hv = *(const float2 *)(gh + (size_t)(i0 + t) * HH + 2 * lane);
            buf[t * 40 + sl] = packh(hv.x, hv.y);
        }
        __syncwarp();

        float acc[2][8][4];
        zacc(acc);
        gemmH<40, 40, 4>(acc, buf, smu + ND_W1A, g, q);
        __syncwarp();

        // stage agg fp16 (overwrite h staging); zero agg
#pragma unroll
        for (int t = 0; t < 32; t++) {
            size_t ro = (size_t)(i0 + t) * HH;
            float2 av = *(const float2 *)(gagg + ro + 2 * lane);
            *(float2 *)(gagg + ro + 2 * lane) = make_float2(0.f, 0.f);
            buf[t * 40 + sl] = packh(av.x, av.y);
        }
        __syncwarp();
        gemmH<40, 40, 4>(acc, buf, smu + ND_W1B, g, q);  // accumulate
        __syncwarp();

        // m1 = silu(acc + nb1) -> A-fragments in registers
        uint32_t mreg[2][8][2];
#pragma unroll
        for (int m = 0; m < 2; m++) {
#pragma unroll
            for (int n = 0; n < 8; n++) {
                int c0 = 8 * n + 2 * q;
                float2 bb = *(const float2 *)(sm + ND_NB1 + c0);
                mreg[m][n][0] = packh(siluf(acc[m][n][0] + bb.x),
                                      siluf(acc[m][n][1] + bb.y));
                mreg[m][n][1] = packh(siluf(acc[m][n][2] + bb.x),
                                      siluf(acc[m][n][3] + bb.y));
            }
        }

        zacc(acc);
        gemmR<40>(acc, mreg, smu + ND_W2T, g, q);

        // hnew = h_old + acc + nb2 -> global; pack hnew for pre gemms
#pragma unroll
        for (int m = 0; m < 2; m++) {
            int r0 = 16 * m + g, r1 = r0 + 8;
            float *h0 = gh + (size_t)(i0 + r0) * HH;
            float *h1 = gh + (size_t)(i0 + r1) * HH;
#pragma unroll
            for (int n = 0; n < 8; n++) {
                int c0 = 8 * n + 2 * q;
                float2 bb = *(const float2 *)(sm + ND_NB2 + c0);
                float2 o0 = *(const float2 *)(h0 + c0);
                float2 o1 = *(const float2 *)(h1 + c0);
                o0.x += acc[m][n][0] + bb.x;
                o0.y += acc[m][n][1] + bb.y;
                o1.x += acc[m][n][2] + bb.x;
                o1.y += acc[m][n][3] + bb.y;
                *(float2 *)(h0 + c0) = o0;
                *(float2 *)(h1 + c0) = o1;
                if (do_pre) {
                    mreg[m][n][0] = packh(o0.x, o0.y);
                    mreg[m][n][1] = packh(o1.x, o1.y);
                }
            }
        }

        if (do_pre) {
            zacc(acc);
            gemmR<40>(acc, mreg, smu + ND_AT, g, q);
#pragma unroll
            for (int m = 0; m < 2; m++) {
                int r0 = 16 * m + g, r1 = r0 + 8;
#pragma unroll
                for (int n = 0; n < 8; n++) {
                    int w = 4 * n + q;
                    float2 bb = *(const float2 *)(sm + ND_EB1 + 2 * w);
                    gau[(size_t)(i0 + r0) * 32 + w] =
                        packh(acc[m][n][0] + bb.x, acc[m][n][1] + bb.y);
                    gau[(size_t)(i0 + r1) * 32 + w] =
                        packh(acc[m][n][2] + bb.x, acc[m][n][3] + bb.y);
                }
            }
            zacc(acc);
            gemmR<40>(acc, mreg, smu + ND_BT, g, q);
#pragma unroll
            for (int m = 0; m < 2; m++) {
                int r0 = 16 * m + g, r1 = r0 + 8;
#pragma unroll
                for (int n = 0; n < 8; n++) {
                    int w = 4 * n + q;
                    gbu[(size_t)(i0 + r0) * 32 + w] =
                        packh(acc[m][n][0], acc[m][n][1]);
                    gbu[(size_t)(i0 + r1) * 32 + w] =
                        packh(acc[m][n][2], acc[m][n][3]);
                }
            }
        }

        // x += dx; update padded coords; reset dx (lane = node)
        int i = i0 + lane;
        float4 xv = g_x4[i];
        xv.x += g_dx[3 * i + 0];
        xv.y += g_dx[3 * i + 1];
        xv.z += g_dx[3 * i + 2];
        g_x4[i] = xv;
        xout[3 * i + 0] = xv.x;
        xout[3 * i + 1] = xv.y;
        xout[3 * i + 2] = xv.z;
        g_dx[3 * i + 0] = 0.f;
        g_dx[3 * i + 1] = 0.f;
        g_dx[3 * i + 2] = 0.f;
        __syncwarp();
    }
}

// ---------------- launch ----------------
extern "C" void kernel_launch(void *const *d_in, const int *in_sizes, int n_in,
                              void *d_out, int out_size) {
    const float *x   = (const float *)d_in[0];
    const int   *z   = (const int *)d_in[1];
    const float *t   = (const float *)d_in[2];
    const int   *ei  = (const int *)d_in[3];
    const float *emb = (const float *)d_in[4];
    const float *tw1 = (const float *)d_in[5];
    const float *tb1 = (const float *)d_in[6];
    const float *tw2 = (const float *)d_in[7];
    const float *tb2 = (const float *)d_in[8];
    const float *ew1 = (const float *)d_in[9];
    const float *eb1 = (const float *)d_in[10];
    const float *ew2 = (const float *)d_in[11];
    const float *eb2 = (const float *)d_in[12];
    const float *cw1 = (const float *)d_in[13];
    const float *cb1 = (const float *)d_in[14];
    const float *cw2 = (const float *)d_in[15];
    const float *cb2 = (const float *)d_in[16];
    const float *nw1 = (const float *)d_in[17];
    const float *nb1 = (const float *)d_in[18];
    const float *nw2 = (const float *)d_in[19];
    const float *nb2 = (const float *)d_in[20];
    float *out = (float *)d_out;

    cudaFuncSetAttribute(edge_kernel, cudaFuncAttributeMaxDynamicSharedMemorySize,
                         EDGE_SMEM_BYTES);
    cudaFuncSetAttribute(node_kernel, cudaFuncAttributeMaxDynamicSharedMemorySize,
                         NODE_SMEM_BYTES);
    cudaFuncSetAttribute(pre0_kernel, cudaFuncAttributeMaxDynamicSharedMemorySize,
                         PRE_SMEM_BYTES);

    tmean_kernel<<<1, 64>>>(t, tw1, tb1, tw2, tb2);
    init_kernel<<<2048, 256>>>(x, z, emb, out);
    pre0_kernel<<<296, 256, PRE_SMEM_BYTES>>>(ew1, eb1);
    for (int l = 0; l < NLAYERS; l++) {
        edge_kernel<<<444, 256, EDGE_SMEM_BYTES>>>(
            ei, ew1 + l * 8256, ew2 + l * 4096, eb2 + l * 64,
            cw1 + l * 4096, cb1 + l * 64, cw2 + l * 64, cb2 + l);
        int do_pre = (l + 1 < NLAYERS);
        node_kernel<<<296, 256, NODE_SMEM_BYTES>>>(
            out, nw1 + l * 8192, nb1 + l * 64, nw2 + l * 4096, nb2 + l * 64,
            do_pre ? (ew1 + (l + 1) * 8256) : ew1,
            do_pre ? (eb1 + (l + 1) * 64) : eb1, do_pre);
    }
    (void)in_sizes; (void)n_in; (void)out_size;
}

// round 15
// speedup vs baseline: 1.3018x; 1.0540x over previous
#include <cuda_runtime.h>
#include <cuda_fp16.h>
#include <cstdint>

#define NN 100000
#define NE 1600000
#define HH 64
#define NLAYERS 3

// ---------------- device scratch ----------------
__device__ float4 g_h4[NN * 16];     // h: (N, 64) fp32
__device__ float4 g_agg4[NN * 16];   // agg: (N, 64) fp32 (true col order)
__device__ __half2 g_ah[NN * 32];    // a[n] = h[n] @ W1[0:64] + e_b1 (fp16)
__device__ __half2 g_bh[NN * 32];    // b[n] = h[n] @ W1[64:128]      (fp16)
__device__ float4 g_x4[NN];          // padded coords (x,y,z,0)
__device__ float4 g_dx4[NN];         // coordinate deltas (padded)
__device__ float4 g_tmean4[16];

// ---------------- helpers ----------------
__device__ __forceinline__ float siluf(float v) {
    float th;
    float hv = 0.5f * v;
    asm("tanh.approx.f32 %0, %1;" : "=f"(th) : "f"(hv));
    return fmaf(hv, th, hv);
}
__device__ __forceinline__ float silux(float v) {
    return __fdividef(v, 1.0f + __expf(-v));
}
// packed half2 silu: silu(x) = 0.5x + 0.5x*tanh(0.5x)
__device__ __forceinline__ uint32_t silu_h2(uint32_t x) {
    uint32_t hv, th, r;
    asm("mul.rn.f16x2 %0, %1, %2;" : "=r"(hv) : "r"(x), "r"(0x38003800u));
    asm("tanh.approx.f16x2 %0, %1;" : "=r"(th) : "r"(hv));
    asm("fma.rn.f16x2 %0, %1, %2, %3;" : "=r"(r) : "r"(hv), "r"(th), "r"(hv));
    return r;
}
__device__ __forceinline__ uint32_t hadd2u(uint32_t a, uint32_t b) {
    uint32_t r;
    asm("add.rn.f16x2 %0, %1, %2;" : "=r"(r) : "r"(a), "r"(b));
    return r;
}
__device__ __forceinline__ uint32_t hmul2u(uint32_t a, uint32_t b) {
    uint32_t r;
    asm("mul.rn.f16x2 %0, %1, %2;" : "=r"(r) : "r"(a), "r"(b));
    return r;
}
__device__ __forceinline__ float2 h2f2(uint32_t h) {
    __half2 hh = *reinterpret_cast<__half2 *>(&h);
    return __half22float2(hh);
}
__device__ __forceinline__ void red4(float *p, float a, float b, float c,
                                     float d) {
    asm volatile("red.global.add.v4.f32 [%0], {%1,%2,%3,%4};" ::"l"(p), "f"(a),
                 "f"(b), "f"(c), "f"(d)
                 : "memory");
}
__device__ __forceinline__ uint32_t packh(float a, float b) {
    __half2 h = __floats2half2_rn(a, b);
    return *reinterpret_cast<uint32_t *>(&h);
}
// pair-slot index for fp16x2 word w (= k/2) within a row
__device__ __forceinline__ int pslot(int w) {
    return 8 * (w >> 3) + 2 * (w & 3) + ((w >> 2) & 1);
}
// fragment col -> physical col permutation (makes quad outputs 16B-contig)
__device__ __forceinline__ int physcol(int c) {
    int n = c >> 3, q = (c >> 1) & 3, j = c & 1;
    return 16 * (n >> 1) + 4 * q + 2 * (n & 1) + j;
}
// fp32-accum mma (node/pre path)
__device__ __forceinline__ void mma_f16(float (&d)[4], uint32_t a0, uint32_t a1,
                                        uint32_t a2, uint32_t a3, uint32_t b0,
                                        uint32_t b1) {
    asm volatile(
        "mma.sync.aligned.m16n8k16.row.col.f32.f16.f16.f32 "
        "{%0,%1,%2,%3}, {%4,%5,%6,%7}, {%8,%9}, {%0,%1,%2,%3};\n"
        : "+f"(d[0]), "+f"(d[1]), "+f"(d[2]), "+f"(d[3])
        : "r"(a0), "r"(a1), "r"(a2), "r"(a3), "r"(b0), "r"(b1));
}
// f16-accum mma (edge path)
__device__ __forceinline__ void mma_f16d(uint32_t (&d)[2], uint32_t a0,
                                         uint32_t a1, uint32_t a2, uint32_t a3,
                                         uint32_t b0, uint32_t b1) {
    asm volatile(
        "mma.sync.aligned.m16n8k16.row.col.f16.f16.f16.f16 "
        "{%0,%1}, {%2,%3,%4,%5}, {%6,%7}, {%0,%1};\n"
        : "+r"(d[0]), "+r"(d[1])
        : "r"(a0), "r"(a1), "r"(a2), "r"(a3), "r"(b0), "r"(b1));
}

// ---- fp32-acc gemms (node/pre) ----
template <int SA, int SB, int KS16>
__device__ __forceinline__ void gemmH(float (&acc)[2][8][4],
                                      const uint32_t *__restrict__ A,
                                      const uint32_t *__restrict__ B, int g,
                                      int q) {
#pragma unroll
    for (int ks = 0; ks < KS16; ks++) {
        uint2 bf[8];
#pragma unroll
        for (int n = 0; n < 8; n++)
            bf[n] = *(const uint2 *)(B + (8 * n + g) * SB + 8 * ks + 2 * q);
#pragma unroll
        for (int m = 0; m < 2; m++) {
            const uint32_t *ap = A + (16 * m + g) * SA + 8 * ks + 2 * q;
            uint2 lo = *(const uint2 *)ap;
            uint2 hi = *(const uint2 *)(ap + 8 * SA);
#pragma unroll
            for (int n = 0; n < 8; n++)
                mma_f16(acc[m][n], lo.x, hi.x, lo.y, hi.y, bf[n].x, bf[n].y);
        }
    }
}
template <int SB>
__device__ __forceinline__ void gemmR(float (&acc)[2][8][4],
                                      const uint32_t (&Ar)[2][8][2],
                                      const uint32_t *__restrict__ B, int g,
                                      int q) {
#pragma unroll
    for (int ks = 0; ks < 4; ks++) {
        uint2 bf[8];
#pragma unroll
        for (int n = 0; n < 8; n++)
            bf[n] = *(const uint2 *)(B + (8 * n + g) * SB + 8 * ks + 2 * q);
#pragma unroll
        for (int m = 0; m < 2; m++) {
#pragma unroll
            for (int n = 0; n < 8; n++)
                mma_f16(acc[m][n], Ar[m][2 * ks][0], Ar[m][2 * ks][1],
                        Ar[m][2 * ks + 1][0], Ar[m][2 * ks + 1][1], bf[n].x,
                        bf[n].y);
        }
    }
}
// ---- f16-acc gemms (edge) ----
template <int SA, int SB, int KS16>
__device__ __forceinline__ void gemmH16(uint32_t (&acc)[2][8][2],
                                        const uint32_t *__restrict__ A,
                                        const uint32_t *__restrict__ B, int g,
                                        int q) {
#pragma unroll
    for (int ks = 0; ks < KS16; ks++) {
        uint2 bf[8];
#pragma unroll
        for (int n = 0; n < 8; n++)
            bf[n] = *(const uint2 *)(B + (8 * n + g) * SB + 8 * ks + 2 * q);
#pragma unroll
        for (int m = 0; m < 2; m++) {
            const uint32_t *ap = A + (16 * m + g) * SA + 8 * ks + 2 * q;
            uint2 lo = *(const uint2 *)ap;
            uint2 hi = *(const uint2 *)(ap + 8 * SA);
#pragma unroll
            for (int n = 0; n < 8; n++)
                mma_f16d(acc[m][n], lo.x, hi.x, lo.y, hi.y, bf[n].x, bf[n].y);
        }
    }
}
template <int SB>
__device__ __forceinline__ void gemmR16(uint32_t (&acc)[2][8][2],
                                        const uint32_t (&Ar)[2][8][2],
                                        const uint32_t *__restrict__ B, int g,
                                        int q) {
#pragma unroll
    for (int ks = 0; ks < 4; ks++) {
        uint2 bf[8];
#pragma unroll
        for (int n = 0; n < 8; n++)
            bf[n] = *(const uint2 *)(B + (8 * n + g) * SB + 8 * ks + 2 * q);
#pragma unroll
        for (int m = 0; m < 2; m++) {
#pragma unroll
            for (int n = 0; n < 8; n++)
                mma_f16d(acc[m][n], Ar[m][2 * ks][0], Ar[m][2 * ks][1],
                         Ar[m][2 * ks + 1][0], Ar[m][2 * ks + 1][1], bf[n].x,
                         bf[n].y);
        }
    }
}
__device__ __forceinline__ void zacc(float (&acc)[2][8][4]) {
#pragma unroll
    for (int m = 0; m < 2; m++)
#pragma unroll
        for (int n = 0; n < 8; n++)
#pragma unroll
            for (int v = 0; v < 4; v++) acc[m][n][v] = 0.f;
}
__device__ __forceinline__ void zacc16(uint32_t (&acc)[2][8][2]) {
#pragma unroll
    for (int m = 0; m < 2; m++)
#pragma unroll
        for (int n = 0; n < 8; n++) {
            acc[m][n][0] = 0u;
            acc[m][n][1] = 0u;
        }
}
__device__ __forceinline__ void cp_s(float *dst, const float *__restrict__ src,
                                     int nfloats, int tid, int nthr) {
    const float4 *s4 = (const float4 *)src;
    float4 *d4 = (float4 *)dst;
    for (int k = tid; k < (nfloats >> 2); k += nthr) d4[k] = s4[k];
}
// stage K x 64 row-major fp32 weights into fp16x2 pair-slot [64][stride]
__device__ __forceinline__ void stage_w16(uint32_t *dst, const float *__restrict__ W,
                                          int kwords, int stride, int tid,
                                          int nthr) {
    for (int idx = tid; idx < 64 * kwords; idx += nthr) {
        int n = idx / kwords, w = idx % kwords;
        dst[n * stride + pslot(w)] =
            packh(W[(2 * w) * 64 + n], W[(2 * w + 1) * 64 + n]);
    }
}
// W2 staged with OUTPUT-column permutation (frag col c -> W2 col physcol(c))
__device__ __forceinline__ void stage_w16_colperm(uint32_t *dst,
                                                  const float *__restrict__ W,
                                                  int tid, int nthr) {
    for (int idx = tid; idx < 64 * 32; idx += nthr) {
        int c = idx >> 5, w = idx & 31;
        int p = physcol(c);
        dst[c * 40 + pslot(w)] =
            packh(W[(2 * w) * 64 + p], W[(2 * w + 1) * 64 + p]);
    }
}
// C1 staged with K-row permutation (frag k index kf -> C1 row physcol(kf))
__device__ __forceinline__ void stage_w16_kperm(uint32_t *dst,
                                                const float *__restrict__ W,
                                                int tid, int nthr) {
    for (int idx = tid; idx < 64 * 32; idx += nthr) {
        int o = idx >> 5, w = idx & 31;
        int pk = physcol(2 * w);  // physcol(2w+1) == physcol(2w)+1
        dst[o * 40 + pslot(w)] = packh(W[pk * 64 + o], W[(pk + 1) * 64 + o]);
    }
}

// ---------------- time-embedding mean ----------------
__global__ void tmean_kernel(const float *__restrict__ t,
                             const float *__restrict__ w1,
                             const float *__restrict__ b1,
                             const float *__restrict__ w2,
                             const float *__restrict__ b2) {
    __shared__ float sS[16 * 64];
    int j = threadIdx.x;
    float w1j = w1[j], b1j = b1[j];
    for (int b = 0; b < 16; b++) sS[b * 64 + j] = silux(t[b] * w1j + b1j);
    __syncthreads();
    float accm = 0.f;
    for (int b = 0; b < 16; b++) {
        float s = b2[j];
        for (int k = 0; k < 64; k++) s += sS[b * 64 + k] * w2[k * 64 + j];
        accm += s;
    }
    ((float *)g_tmean4)[j] = accm * (1.0f / 16.0f);
}

// ---------------- init ----------------
__global__ void init_kernel(const float *__restrict__ x, const int *__restrict__ z,
                            const float *__restrict__ emb, float *__restrict__ out) {
    int tid = blockIdx.x * blockDim.x + threadIdx.x;
    int stride = gridDim.x * blockDim.x;
    const float4 *emb4 = (const float4 *)emb;
    for (int idx = tid; idx < NN * 16; idx += stride) {
        int i = idx >> 4, qq = idx & 15;
        float4 e = emb4[z[i] * 16 + qq];
        float4 tm = g_tmean4[qq];
        float4 r;
        r.x = e.x + tm.x; r.y = e.y + tm.y; r.z = e.z + tm.z; r.w = e.w + tm.w;
        g_h4[idx] = r;
        g_agg4[idx] = make_float4(0.f, 0.f, 0.f, 0.f);
    }
    for (int idx = tid; idx < NN * 3; idx += stride) {
        out[idx] = x[idx];
    }
    for (int i = tid; i < NN; i += stride) {
        g_x4[i] = make_float4(x[3 * i], x[3 * i + 1], x[3 * i + 2], 0.f);
        g_dx4[i] = make_float4(0.f, 0.f, 0.f, 0.f);
    }
}

// ---------------- pre0: a,b for layer 0 (fp16 tensor core) ----------------
#define PR_AT 0
#define PR_BT 2560
#define PR_EB1 5120
#define PR_WARP 5184
#define PR_WARP_WORDS 1280
#define PRE_SMEM_BYTES ((PR_WARP + 8 * PR_WARP_WORDS) * 4)

__global__ void __launch_bounds__(256, 2)
pre0_kernel(const float *__restrict__ W1, const float *__restrict__ B1) {
    extern __shared__ float sm[];
    uint32_t *smu = (uint32_t *)sm;
    int tid = threadIdx.x;
    stage_w16(smu + PR_AT, W1, 32, 40, tid, 256);
    stage_w16(smu + PR_BT, W1 + 64 * 64, 32, 40, tid, 256);
    cp_s(sm + PR_EB1, B1, 64, tid, 256);
    __syncthreads();

    const int lane = tid & 31, wid = tid >> 5;
    const int g = lane >> 2, q = lane & 3;
    uint32_t *buf = smu + PR_WARP + wid * PR_WARP_WORDS;
    const float *gh = (const float *)g_h4;
    const int sl = pslot(lane);

    int gwarp = blockIdx.x * 8 + wid;
    int nwarps = gridDim.x * 8;
    for (int i0 = gwarp * 32; i0 < NN; i0 += nwarps * 32) {
#pragma unroll
        for (int t = 0; t < 32; t++) {
            float2 hv = *(const float2 *)(gh + (size_t)(i0 + t) * HH + 2 * lane);
            buf[t * 40 + sl] = packh(hv.x, hv.y);
        }
        __syncwarp();
        float acc[2][8][4];
        zacc(acc);
        gemmH<40, 40, 4>(acc, buf, smu + PR_AT, g, q);
#pragma unroll
        for (int m = 0; m < 2; m++) {
            int r0 = 16 * m + g, r1 = r0 + 8;
#pragma unroll
            for (int n = 0; n < 8; n++) {
                int w = 4 * n + q;
                float2 bb = *(const float2 *)(sm + PR_EB1 + 2 * w);
                g_ah[(size_t)(i0 + r0) * 32 + w] =
                    __floats2half2_rn(acc[m][n][0] + bb.x, acc[m][n][1] + bb.y);
                g_ah[(size_t)(i0 + r1) * 32 + w] =
                    __floats2half2_rn(acc[m][n][2] + bb.x, acc[m][n][3] + bb.y);
            }
        }
        zacc(acc);
        gemmH<40, 40, 4>(acc, buf, smu + PR_BT, g, q);
#pragma unroll
        for (int m = 0; m < 2; m++) {
            int r0 = 16 * m + g, r1 = r0 + 8;
#pragma unroll
            for (int n = 0; n < 8; n++) {
                int w = 4 * n + q;
                g_bh[(size_t)(i0 + r0) * 32 + w] =
                    __floats2half2_rn(acc[m][n][0], acc[m][n][1]);
                g_bh[(size_t)(i0 + r1) * 32 + w] =
                    __floats2half2_rn(acc[m][n][2], acc[m][n][3]);
            }
        }
        __syncwarp();
    }
}

// ---------------- edge kernel (f16-acc TC, col-perm red4 epilogue) ---------
#define E_W2T 0
#define E_C1T 2560
#define E_B2H 5120
#define E_CB1H 5152
#define E_C2H 5184
#define E_W129 5216
#define E_CB2 5280
#define E_WARP 5284
#define E_WARP_WORDS 1312   /* m1s 1280 + cwbuf 32 */
#define EDGE_SMEM_BYTES ((E_WARP + 8 * E_WARP_WORDS) * 4)

__global__ void __launch_bounds__(256, 3)
edge_kernel(const int *__restrict__ ei, const float *__restrict__ W1,
            const float *__restrict__ W2, const float *__restrict__ B2,
            const float *__restrict__ C1, const float *__restrict__ Cb1,
            const float *__restrict__ C2, const float *__restrict__ Cb2) {
    extern __shared__ float sm[];
    uint32_t *smu = (uint32_t *)sm;
    int tid = threadIdx.x;

    stage_w16_colperm(smu + E_W2T, W2, tid, 256);
    stage_w16_kperm(smu + E_C1T, C1, tid, 256);
    if (tid < 32) {
        // b2 in permuted fragment order: word u covers frag cols (8n+2q, +1)
        int c0 = 8 * (tid >> 2) + 2 * (tid & 3);
        int p0 = physcol(c0);
        smu[E_B2H + tid] = packh(B2[p0], B2[p0 + 1]);
        smu[E_CB1H + tid] = packh(Cb1[2 * tid], Cb1[2 * tid + 1]);
        smu[E_C2H + tid] = packh(C2[2 * tid], C2[2 * tid + 1]);
    }
    cp_s(sm + E_W129, W1 + 8192, 64, tid, 256);
    if (tid == 0) sm[E_CB2] = Cb2[0];
    __syncthreads();

    const int lane = tid & 31;
    const int wid = tid >> 5;
    const int g = lane >> 2;
    const int q = lane & 3;
    uint32_t *m1s = smu + E_WARP + wid * E_WARP_WORDS;
    float *cwbuf = sm + E_WARP + wid * E_WARP_WORDS + 1280;
    const int sl = pslot(lane);

    float *gagg = (float *)g_agg4;
    const uint32_t *gau = (const uint32_t *)g_ah;
    const uint32_t *gbu = (const uint32_t *)g_bh;

    const float w129x = sm[E_W129 + 2 * lane];
    const float w129y = sm[E_W129 + 2 * lane + 1];
    const float cb2v = sm[E_CB2];

    int gwarp = blockIdx.x * 8 + wid;
    int nwarps = gridDim.x * 8;

    for (int eb = gwarp * 32; eb < NE; eb += nwarps * 32) {
        int e = eb + lane;
        int s = ei[e];
        int d = ei[NE + e];
        float4 xd = g_x4[d];
        float4 xs = g_x4[s];
        float ax = xd.x - xs.x;
        float ay = xd.y - xs.y;
        float az = xd.z - xs.z;
        float d2 = ax * ax + ay * ay + az * az;

        // m1 = silu(a[d] + b[s] + d2*w129) -> staged fp16 pair-slot
#pragma unroll
        for (int t = 0; t < 32; t++) {
            int dt = __shfl_sync(0xffffffffu, d, t);
            int st = __shfl_sync(0xffffffffu, s, t);
            float d2t = __shfl_sync(0xffffffffu, d2, t);
            float2 av = h2f2(gau[(size_t)dt * 32 + lane]);
            float2 bv = h2f2(gbu[(size_t)st * 32 + lane]);
            float m0 = siluf(fmaf(d2t, w129x, av.x + bv.x));
            float m1v = siluf(fmaf(d2t, w129y, av.y + bv.y));
            m1s[t * 40 + sl] = packh(m0, m1v);
        }
        __syncwarp();

        // GEMM2 (f16 acc): frag col c holds output physcol(c)
        uint32_t acc[2][8][2];
        zacc16(acc);
        gemmH16<40, 40, 4>(acc, m1s, smu + E_W2T, g, q);

        // epilogue: bias+silu in h2; agg scatter via 16B-contig red4
        uint32_t mreg[2][8][2];
#pragma unroll
        for (int m = 0; m < 2; m++) {
            int r0 = 16 * m + g;
            int r1 = r0 + 8;
            int d0 = __shfl_sync(0xffffffffu, d, r0);
            int d1 = __shfl_sync(0xffffffffu, d, r1);
            float *agg0 = gagg + (size_t)d0 * HH;
            float *agg1 = gagg + (size_t)d1 * HH;
#pragma unroll
            for (int P = 0; P < 4; P++) {
                int n0 = 2 * P, n1 = n0 + 1;
                uint32_t b0h = smu[E_B2H + 4 * n0 + q];
                uint32_t b1h = smu[E_B2H + 4 * n1 + q];
                uint32_t v00 = silu_h2(hadd2u(acc[m][n0][0], b0h));
                uint32_t v10 = silu_h2(hadd2u(acc[m][n1][0], b1h));
                uint32_t v01 = silu_h2(hadd2u(acc[m][n0][1], b0h));
                uint32_t v11 = silu_h2(hadd2u(acc[m][n1][1], b1h));
                float2 f00 = h2f2(v00), f10 = h2f2(v10);
                float2 f01 = h2f2(v01), f11 = h2f2(v11);
                int cc = 16 * P + 4 * q;
                red4(agg0 + cc, f00.x, f00.y, f10.x, f10.y);
                red4(agg1 + cc, f01.x, f01.y, f11.x, f11.y);
                mreg[m][n0][0] = v00;
                mreg[m][n0][1] = v01;
                mreg[m][n1][0] = v10;
                mreg[m][n1][1] = v11;
            }
        }

        // coord MLP (f16 acc): C1 staged with matching K perm
        zacc16(acc);
        gemmR16<40>(acc, mreg, smu + E_C1T, g, q);

        float cwp[2][2] = {{0.f, 0.f}, {0.f, 0.f}};
#pragma unroll
        for (int m = 0; m < 2; m++)
#pragma unroll
            for (int n = 0; n < 8; n++) {
                uint32_t cb1h = smu[E_CB1H + 4 * n + q];
                uint32_t c2h = smu[E_C2H + 4 * n + q];
                uint32_t p0 = hmul2u(silu_h2(hadd2u(acc[m][n][0], cb1h)), c2h);
                uint32_t p1 = hmul2u(silu_h2(hadd2u(acc[m][n][1], cb1h)), c2h);
                float2 f0 = h2f2(p0);
                float2 f1 = h2f2(p1);
                cwp[m][0] += f0.x + f0.y;
                cwp[m][1] += f1.x + f1.y;
            }
#pragma unroll
        for (int ofs = 1; ofs <= 2; ofs <<= 1) {
#pragma unroll
            for (int m = 0; m < 2; m++) {
                cwp[m][0] += __shfl_xor_sync(0xffffffffu, cwp[m][0], ofs);
                cwp[m][1] += __shfl_xor_sync(0xffffffffu, cwp[m][1], ofs);
            }
        }
        if (q == 0) {
#pragma unroll
            for (int m = 0; m < 2; m++) {
                cwbuf[16 * m + g] = cwp[m][0] + cb2v;
                cwbuf[16 * m + g + 8] = cwp[m][1] + cb2v;
            }
        }
        __syncwarp();

        float cw = cwbuf[lane];
        red4((float *)&g_dx4[d], ax * cw, ay * cw, az * cw, 0.f);
        __syncwarp();
    }
}

// ---------------- node kernel (fp32-acc TC, split-K, reg A-reuse) ----------
#define ND_W1A 0
#define ND_W1B 2560
#define ND_W2T 5120
#define ND_AT 7680
#define ND_BT 10240
#define ND_NB1 12800
#define ND_NB2 12864
#define ND_EB1 12928
#define ND_WARP 12992
#define ND_WARP_WORDS 1280
#define NODE_SMEM_BYTES ((ND_WARP + 8 * ND_WARP_WORDS) * 4)

__global__ void __launch_bounds__(256, 2)
node_kernel(float *__restrict__ xout, const float *__restrict__ NW1,
            const float *__restrict__ NB1, const float *__restrict__ NW2,
            const float *__restrict__ NB2, const float *__restrict__ EW1n,
            const float *__restrict__ EB1n, int do_pre) {
    extern __shared__ float sm[];
    uint32_t *smu = (uint32_t *)sm;
    int tid = threadIdx.x;

    stage_w16(smu + ND_W1A, NW1, 32, 40, tid, 256);           // nf rows 0..63 (h)
    stage_w16(smu + ND_W1B, NW1 + 64 * 64, 32, 40, tid, 256); // rows 64..127 (agg)
    stage_w16(smu + ND_W2T, NW2, 32, 40, tid, 256);
    if (do_pre) {
        stage_w16(smu + ND_AT, EW1n, 32, 40, tid, 256);
        stage_w16(smu + ND_BT, EW1n + 64 * 64, 32, 40, tid, 256);
    }
    cp_s(sm + ND_NB1, NB1, 64, tid, 256);
    cp_s(sm + ND_NB2, NB2, 64, tid, 256);
    if (do_pre) cp_s(sm + ND_EB1, EB1n, 64, tid, 256);
    __syncthreads();

    const int lane = tid & 31, wid = tid >> 5;
    const int g = lane >> 2, q = lane & 3;
    uint32_t *buf = smu + ND_WARP + wid * ND_WARP_WORDS;
    const int sl = pslot(lane);

    float *gh = (float *)g_h4;
    float *gagg = (float *)g_agg4;
    uint32_t *gau = (uint32_t *)g_ah;
    uint32_t *gbu = (uint32_t *)g_bh;

    int gwarp = blockIdx.x * 8 + wid;
    int nwarps = gridDim.x * 8;

    for (int i0 = gwarp * 32; i0 < NN; i0 += nwarps * 32) {
        // stage h fp16 (stride 40)
#pragma unroll
        for (int t = 0; t < 32; t++) {
            float2 hv = *(const float2 *)(gh + (size_t)(i0 + t) * HH + 2 * lane);
            buf[t * 40 + sl] = packh(hv.x, hv.y);
        }
        __syncwarp();

        float acc[2][8][4];
        zacc(acc);
        gemmH<40, 40, 4>(acc, buf, smu + ND_W1A, g, q);
        __syncwarp();

        // stage agg fp16 (overwrite h staging); zero agg
#pragma unroll
        for (int t = 0; t < 32; t++) {
            size_t ro = (size_t)(i0 + t) * HH;
            float2 av = *(const float2 *)(gagg + ro + 2 * lane);
            *(float2 *)(gagg + ro + 2 * lane) = make_float2(0.f, 0.f);
            buf[t * 40 + sl] = packh(av.x, av.y);
        }
        __syncwarp();
        gemmH<40, 40, 4>(acc, buf, smu + ND_W1B, g, q);  // accumulate
        __syncwarp();

        // m1 = silu(acc + nb1) -> A-fragments in registers
        uint32_t mreg[2][8][2];
#pragma unroll
        for (int m = 0; m < 2; m++) {
#pragma unroll
            for (int n = 0; n < 8; n++) {
                int c0 = 8 * n + 2 * q;
                float2 bb = *(const float2 *)(sm + ND_NB1 + c0);
                mreg[m][n][0] = packh(siluf(acc[m][n][0] + bb.x),
                                      siluf(acc[m][n][1] + bb.y));
                mreg[m][n][1] = packh(siluf(acc[m][n][2] + bb.x),
                                      siluf(acc[m][n][3] + bb.y));
            }
        }

        zacc(acc);
        gemmR<40>(acc, mreg, smu + ND_W2T, g, q);

        // hnew = h_old + acc + nb2 -> global; pack hnew for pre gemms
#pragma unroll
        for (int m = 0; m < 2; m++) {
            int r0 = 16 * m + g, r1 = r0 + 8;
            float *h0 = gh + (size_t)(i0 + r0) * HH;
            float *h1 = gh + (size_t)(i0 + r1) * HH;
#pragma unroll
            for (int n = 0; n < 8; n++) {
                int c0 = 8 * n + 2 * q;
                float2 bb = *(const float2 *)(sm + ND_NB2 + c0);
                float2 o0 = *(const float2 *)(h0 + c0);
                float2 o1 = *(const float2 *)(h1 + c0);
                o0.x += acc[m][n][0] + bb.x;
                o0.y += acc[m][n][1] + bb.y;
                o1.x += acc[m][n][2] + bb.x;
                o1.y += acc[m][n][3] + bb.y;
                *(float2 *)(h0 + c0) = o0;
                *(float2 *)(h1 + c0) = o1;
                if (do_pre) {
                    mreg[m][n][0] = packh(o0.x, o0.y);
                    mreg[m][n][1] = packh(o1.x, o1.y);
                }
            }
        }

        if (do_pre) {
            zacc(acc);
            gemmR<40>(acc, mreg, smu + ND_AT, g, q);
#pragma unroll
            for (int m = 0; m < 2; m++) {
                int r0 = 16 * m + g, r1 = r0 + 8;
#pragma unroll
                for (int n = 0; n < 8; n++) {
                    int w = 4 * n + q;
                    float2 bb = *(const float2 *)(sm + ND_EB1 + 2 * w);
                    gau[(size_t)(i0 + r0) * 32 + w] =
                        packh(acc[m][n][0] + bb.x, acc[m][n][1] + bb.y);
                    gau[(size_t)(i0 + r1) * 32 + w] =
                        packh(acc[m][n][2] + bb.x, acc[m][n][3] + bb.y);
                }
            }
            zacc(acc);
            gemmR<40>(acc, mreg, smu + ND_BT, g, q);
#pragma unroll
            for (int m = 0; m < 2; m++) {
                int r0 = 16 * m + g, r1 = r0 + 8;
#pragma unroll
                for (int n = 0; n < 8; n++) {
                    int w = 4 * n + q;
                    gbu[(size_t)(i0 + r0) * 32 + w] =
                        packh(acc[m][n][0], acc[m][n][1]);
                    gbu[(size_t)(i0 + r1) * 32 + w] =
                        packh(acc[m][n][2], acc[m][n][3]);
                }
            }
        }

        // x += dx; update padded coords; reset dx (lane = node)
        int i = i0 + lane;
        float4 dxv = g_dx4[i];
        g_dx4[i] = make_float4(0.f, 0.f, 0.f, 0.f);
        float4 xv = g_x4[i];
        xv.x += dxv.x;
        xv.y += dxv.y;
        xv.z += dxv.z;
        g_x4[i] = xv;
        xout[3 * i + 0] = xv.x;
        xout[3 * i + 1] = xv.y;
        xout[3 * i + 2] = xv.z;
        __syncwarp();
    }
}

// ---------------- launch ----------------
extern "C" void kernel_launch(void *const *d_in, const int *in_sizes, int n_in,
                              void *d_out, int out_size) {
    const float *x   = (const float *)d_in[0];
    const int   *z   = (const int *)d_in[1];
    const float *t   = (const float *)d_in[2];
    const int   *ei  = (const int *)d_in[3];
    const float *emb = (const float *)d_in[4];
    const float *tw1 = (const float *)d_in[5];
    const float *tb1 = (const float *)d_in[6];
    const float *tw2 = (const float *)d_in[7];
    const float *tb2 = (const float *)d_in[8];
    const float *ew1 = (const float *)d_in[9];
    const float *eb1 = (const float *)d_in[10];
    const float *ew2 = (const float *)d_in[11];
    const float *eb2 = (const float *)d_in[12];
    const float *cw1 = (const float *)d_in[13];
    const float *cb1 = (const float *)d_in[14];
    const float *cw2 = (const float *)d_in[15];
    const float *cb2 = (const float *)d_in[16];
    const float *nw1 = (const float *)d_in[17];
    const float *nb1 = (const float *)d_in[18];
    const float *nw2 = (const float *)d_in[19];
    const float *nb2 = (const float *)d_in[20];
    float *out = (float *)d_out;

    cudaFuncSetAttribute(edge_kernel, cudaFuncAttributeMaxDynamicSharedMemorySize,
                         EDGE_SMEM_BYTES);
    cudaFuncSetAttribute(node_kernel, cudaFuncAttributeMaxDynamicSharedMemorySize,
                         NODE_SMEM_BYTES);
    cudaFuncSetAttribute(pre0_kernel, cudaFuncAttributeMaxDynamicSharedMemorySize,
                         PRE_SMEM_BYTES);

    tmean_kernel<<<1, 64>>>(t, tw1, tb1, tw2, tb2);
    init_kernel<<<2048, 256>>>(x, z, emb, out);
    pre0_kernel<<<296, 256, PRE_SMEM_BYTES>>>(ew1, eb1);
    for (int l = 0; l < NLAYERS; l++) {
        edge_kernel<<<444, 256, EDGE_SMEM_BYTES>>>(
            ei, ew1 + l * 8256, ew2 + l * 4096, eb2 + l * 64,
            cw1 + l * 4096, cb1 + l * 64, cw2 + l * 64, cb2 + l);
        int do_pre = (l + 1 < NLAYERS);
        node_kernel<<<296, 256, NODE_SMEM_BYTES>>>(
            out, nw1 + l * 8192, nb1 + l * 64, nw2 + l * 4096, nb2 + l * 64,
            do_pre ? (ew1 + (l + 1) * 8256) : ew1,
            do_pre ? (eb1 + (l + 1) * 64) : eb1, do_pre);
    }
    (void)in_sizes; (void)n_in; (void)out_size;
}

// round 16
// speedup vs baseline: 1.3527x; 1.0391x over previous
#include <cuda_runtime.h>
#include <cuda_fp16.h>
#include <cstdint>

#define NN 100000
#define NE 1600000
#define HH 64
#define NLAYERS 3

// ---------------- device scratch ----------------
__device__ float4 g_h4[NN * 16];     // h: (N, 64) fp32
__device__ float4 g_agg4[NN * 16];   // agg: (N, 64) fp32 (true col order)
__device__ __half2 g_ah[NN * 32];    // a[n] = h[n] @ W1[0:64] + e_b1 (fp16)
__device__ __half2 g_bh[NN * 32];    // b[n] = h[n] @ W1[64:128]      (fp16)
__device__ float4 g_x4[NN];          // padded coords (x,y,z,0)
__device__ float4 g_dx4[NN];         // coordinate deltas (padded)
__device__ float4 g_tmean4[16];

// ---------------- helpers ----------------
__device__ __forceinline__ float siluf(float v) {
    float th;
    float hv = 0.5f * v;
    asm("tanh.approx.f32 %0, %1;" : "=f"(th) : "f"(hv));
    return fmaf(hv, th, hv);
}
__device__ __forceinline__ float silux(float v) {
    return __fdividef(v, 1.0f + __expf(-v));
}
// packed half2 silu: silu(x) = 0.5x + 0.5x*tanh(0.5x)
__device__ __forceinline__ uint32_t silu_h2(uint32_t x) {
    uint32_t hv, th, r;
    asm("mul.rn.f16x2 %0, %1, %2;" : "=r"(hv) : "r"(x), "r"(0x38003800u));
    asm("tanh.approx.f16x2 %0, %1;" : "=r"(th) : "r"(hv));
    asm("fma.rn.f16x2 %0, %1, %2, %3;" : "=r"(r) : "r"(hv), "r"(th), "r"(hv));
    return r;
}
__device__ __forceinline__ uint32_t hadd2u(uint32_t a, uint32_t b) {
    uint32_t r;
    asm("add.rn.f16x2 %0, %1, %2;" : "=r"(r) : "r"(a), "r"(b));
    return r;
}
__device__ __forceinline__ uint32_t hmul2u(uint32_t a, uint32_t b) {
    uint32_t r;
    asm("mul.rn.f16x2 %0, %1, %2;" : "=r"(r) : "r"(a), "r"(b));
    return r;
}
__device__ __forceinline__ uint32_t hfma2u(uint32_t a, uint32_t b, uint32_t c) {
    uint32_t r;
    asm("fma.rn.f16x2 %0, %1, %2, %3;" : "=r"(r) : "r"(a), "r"(b), "r"(c));
    return r;
}
__device__ __forceinline__ float2 h2f2(uint32_t h) {
    __half2 hh = *reinterpret_cast<__half2 *>(&h);
    return __half22float2(hh);
}
__device__ __forceinline__ void red4(float *p, float a, float b, float c,
                                     float d) {
    asm volatile("red.global.add.v4.f32 [%0], {%1,%2,%3,%4};" ::"l"(p), "f"(a),
                 "f"(b), "f"(c), "f"(d)
                 : "memory");
}
__device__ __forceinline__ uint32_t packh(float a, float b) {
    __half2 h = __floats2half2_rn(a, b);
    return *reinterpret_cast<uint32_t *>(&h);
}
// pair-slot index for fp16x2 word w (= k/2) within a row
__device__ __forceinline__ int pslot(int w) {
    return 8 * (w >> 3) + 2 * (w & 3) + ((w >> 2) & 1);
}
// fragment col -> physical col permutation (makes quad outputs 16B-contig)
__device__ __forceinline__ int physcol(int c) {
    int n = c >> 3, q = (c >> 1) & 3, j = c & 1;
    return 16 * (n >> 1) + 4 * q + 2 * (n & 1) + j;
}
// fp32-accum mma (node/pre path)
__device__ __forceinline__ void mma_f16(float (&d)[4], uint32_t a0, uint32_t a1,
                                        uint32_t a2, uint32_t a3, uint32_t b0,
                                        uint32_t b1) {
    asm volatile(
        "mma.sync.aligned.m16n8k16.row.col.f32.f16.f16.f32 "
        "{%0,%1,%2,%3}, {%4,%5,%6,%7}, {%8,%9}, {%0,%1,%2,%3};\n"
        : "+f"(d[0]), "+f"(d[1]), "+f"(d[2]), "+f"(d[3])
        : "r"(a0), "r"(a1), "r"(a2), "r"(a3), "r"(b0), "r"(b1));
}
// f16-accum mma (edge path)
__device__ __forceinline__ void mma_f16d(uint32_t (&d)[2], uint32_t a0,
                                         uint32_t a1, uint32_t a2, uint32_t a3,
                                         uint32_t b0, uint32_t b1) {
    asm volatile(
        "mma.sync.aligned.m16n8k16.row.col.f16.f16.f16.f16 "
        "{%0,%1}, {%2,%3,%4,%5}, {%6,%7}, {%0,%1};\n"
        : "+r"(d[0]), "+r"(d[1])
        : "r"(a0), "r"(a1), "r"(a2), "r"(a3), "r"(b0), "r"(b1));
}

// ---- fp32-acc gemms (node/pre) ----
template <int SA, int SB, int KS16>
__device__ __forceinline__ void gemmH(float (&acc)[2][8][4],
                                      const uint32_t *__restrict__ A,
                                      const uint32_t *__restrict__ B, int g,
                                      int q) {
#pragma unroll
    for (int ks = 0; ks < KS16; ks++) {
        uint2 bf[8];
#pragma unroll
        for (int n = 0; n < 8; n++)
            bf[n] = *(const uint2 *)(B + (8 * n + g) * SB + 8 * ks + 2 * q);
#pragma unroll
        for (int m = 0; m < 2; m++) {
            const uint32_t *ap = A + (16 * m + g) * SA + 8 * ks + 2 * q;
            uint2 lo = *(const uint2 *)ap;
            uint2 hi = *(const uint2 *)(ap + 8 * SA);
#pragma unroll
            for (int n = 0; n < 8; n++)
                mma_f16(acc[m][n], lo.x, hi.x, lo.y, hi.y, bf[n].x, bf[n].y);
        }
    }
}
template <int SB>
__device__ __forceinline__ void gemmR(float (&acc)[2][8][4],
                                      const uint32_t (&Ar)[2][8][2],
                                      const uint32_t *__restrict__ B, int g,
                                      int q) {
#pragma unroll
    for (int ks = 0; ks < 4; ks++) {
        uint2 bf[8];
#pragma unroll
        for (int n = 0; n < 8; n++)
            bf[n] = *(const uint2 *)(B + (8 * n + g) * SB + 8 * ks + 2 * q);
#pragma unroll
        for (int m = 0; m < 2; m++) {
#pragma unroll
            for (int n = 0; n < 8; n++)
                mma_f16(acc[m][n], Ar[m][2 * ks][0], Ar[m][2 * ks][1],
                        Ar[m][2 * ks + 1][0], Ar[m][2 * ks + 1][1], bf[n].x,
                        bf[n].y);
        }
    }
}
// ---- f16-acc gemms (edge) ----
template <int SA, int SB, int KS16>
__device__ __forceinline__ void gemmH16(uint32_t (&acc)[2][8][2],
                                        const uint32_t *__restrict__ A,
                                        const uint32_t *__restrict__ B, int g,
                                        int q) {
#pragma unroll
    for (int ks = 0; ks < KS16; ks++) {
        uint2 bf[8];
#pragma unroll
        for (int n = 0; n < 8; n++)
            bf[n] = *(const uint2 *)(B + (8 * n + g) * SB + 8 * ks + 2 * q);
#pragma unroll
        for (int m = 0; m < 2; m++) {
            const uint32_t *ap = A + (16 * m + g) * SA + 8 * ks + 2 * q;
            uint2 lo = *(const uint2 *)ap;
            uint2 hi = *(const uint2 *)(ap + 8 * SA);
#pragma unroll
            for (int n = 0; n < 8; n++)
                mma_f16d(acc[m][n], lo.x, hi.x, lo.y, hi.y, bf[n].x, bf[n].y);
        }
    }
}
template <int SB>
__device__ __forceinline__ void gemmR16(uint32_t (&acc)[2][8][2],
                                        const uint32_t (&Ar)[2][8][2],
                                        const uint32_t *__restrict__ B, int g,
                                        int q) {
#pragma unroll
    for (int ks = 0; ks < 4; ks++) {
        uint2 bf[8];
#pragma unroll
        for (int n = 0; n < 8; n++)
            bf[n] = *(const uint2 *)(B + (8 * n + g) * SB + 8 * ks + 2 * q);
#pragma unroll
        for (int m = 0; m < 2; m++) {
#pragma unroll
            for (int n = 0; n < 8; n++)
                mma_f16d(acc[m][n], Ar[m][2 * ks][0], Ar[m][2 * ks][1],
                         Ar[m][2 * ks + 1][0], Ar[m][2 * ks + 1][1], bf[n].x,
                         bf[n].y);
        }
    }
}
__device__ __forceinline__ void zacc(float (&acc)[2][8][4]) {
#pragma unroll
    for (int m = 0; m < 2; m++)
#pragma unroll
        for (int n = 0; n < 8; n++)
#pragma unroll
            for (int v = 0; v < 4; v++) acc[m][n][v] = 0.f;
}
__device__ __forceinline__ void zacc16(uint32_t (&acc)[2][8][2]) {
#pragma unroll
    for (int m = 0; m < 2; m++)
#pragma unroll
        for (int n = 0; n < 8; n++) {
            acc[m][n][0] = 0u;
            acc[m][n][1] = 0u;
        }
}
__device__ __forceinline__ void cp_s(float *dst, const float *__restrict__ src,
                                     int nfloats, int tid, int nthr) {
    const float4 *s4 = (const float4 *)src;
    float4 *d4 = (float4 *)dst;
    for (int k = tid; k < (nfloats >> 2); k += nthr) d4[k] = s4[k];
}
// stage K x 64 row-major fp32 weights into fp16x2 pair-slot [64][stride]
__device__ __forceinline__ void stage_w16(uint32_t *dst, const float *__restrict__ W,
                                          int kwords, int stride, int tid,
                                          int nthr) {
    for (int idx = tid; idx < 64 * kwords; idx += nthr) {
        int n = idx / kwords, w = idx % kwords;
        dst[n * stride + pslot(w)] =
            packh(W[(2 * w) * 64 + n], W[(2 * w + 1) * 64 + n]);
    }
}
// W2 staged with OUTPUT-column permutation (frag col c -> W2 col physcol(c))
__device__ __forceinline__ void stage_w16_colperm(uint32_t *dst,
                                                  const float *__restrict__ W,
                                                  int tid, int nthr) {
    for (int idx = tid; idx < 64 * 32; idx += nthr) {
        int c = idx >> 5, w = idx & 31;
        int p = physcol(c);
        dst[c * 40 + pslot(w)] =
            packh(W[(2 * w) * 64 + p], W[(2 * w + 1) * 64 + p]);
    }
}
// C1 staged with K-row permutation (frag k index kf -> C1 row physcol(kf))
__device__ __forceinline__ void stage_w16_kperm(uint32_t *dst,
                                                const float *__restrict__ W,
                                                int tid, int nthr) {
    for (int idx = tid; idx < 64 * 32; idx += nthr) {
        int o = idx >> 5, w = idx & 31;
        int pk = physcol(2 * w);  // physcol(2w+1) == physcol(2w)+1
        dst[o * 40 + pslot(w)] = packh(W[pk * 64 + o], W[(pk + 1) * 64 + o]);
    }
}

// ---------------- time-embedding mean ----------------
__global__ void tmean_kernel(const float *__restrict__ t,
                             const float *__restrict__ w1,
                             const float *__restrict__ b1,
                             const float *__restrict__ w2,
                             const float *__restrict__ b2) {
    __shared__ float sS[16 * 64];
    int j = threadIdx.x;
    float w1j = w1[j], b1j = b1[j];
    for (int b = 0; b < 16; b++) sS[b * 64 + j] = silux(t[b] * w1j + b1j);
    __syncthreads();
    float accm = 0.f;
    for (int b = 0; b < 16; b++) {
        float s = b2[j];
        for (int k = 0; k < 64; k++) s += sS[b * 64 + k] * w2[k * 64 + j];
        accm += s;
    }
    ((float *)g_tmean4)[j] = accm * (1.0f / 16.0f);
}

// ---------------- init ----------------
__global__ void init_kernel(const float *__restrict__ x, const int *__restrict__ z,
                            const float *__restrict__ emb, float *__restrict__ out) {
    int tid = blockIdx.x * blockDim.x + threadIdx.x;
    int stride = gridDim.x * blockDim.x;
    const float4 *emb4 = (const float4 *)emb;
    for (int idx = tid; idx < NN * 16; idx += stride) {
        int i = idx >> 4, qq = idx & 15;
        float4 e = emb4[z[i] * 16 + qq];
        float4 tm = g_tmean4[qq];
        float4 r;
        r.x = e.x + tm.x; r.y = e.y + tm.y; r.z = e.z + tm.z; r.w = e.w + tm.w;
        g_h4[idx] = r;
        g_agg4[idx] = make_float4(0.f, 0.f, 0.f, 0.f);
    }
    for (int idx = tid; idx < NN * 3; idx += stride) {
        out[idx] = x[idx];
    }
    for (int i = tid; i < NN; i += stride) {
        g_x4[i] = make_float4(x[3 * i], x[3 * i + 1], x[3 * i + 2], 0.f);
        g_dx4[i] = make_float4(0.f, 0.f, 0.f, 0.f);
    }
}

// ---------------- pre0: a,b for layer 0 (fp16 tensor core) ----------------
#define PR_AT 0
#define PR_BT 2560
#define PR_EB1 5120
#define PR_WARP 5184
#define PR_WARP_WORDS 1280
#define PRE_SMEM_BYTES ((PR_WARP + 8 * PR_WARP_WORDS) * 4)

__global__ void __launch_bounds__(256, 2)
pre0_kernel(const float *__restrict__ W1, const float *__restrict__ B1) {
    extern __shared__ float sm[];
    uint32_t *smu = (uint32_t *)sm;
    int tid = threadIdx.x;
    stage_w16(smu + PR_AT, W1, 32, 40, tid, 256);
    stage_w16(smu + PR_BT, W1 + 64 * 64, 32, 40, tid, 256);
    cp_s(sm + PR_EB1, B1, 64, tid, 256);
    __syncthreads();

    const int lane = tid & 31, wid = tid >> 5;
    const int g = lane >> 2, q = lane & 3;
    uint32_t *buf = smu + PR_WARP + wid * PR_WARP_WORDS;
    const float *gh = (const float *)g_h4;
    const int sl = pslot(lane);

    int gwarp = blockIdx.x * 8 + wid;
    int nwarps = gridDim.x * 8;
    for (int i0 = gwarp * 32; i0 < NN; i0 += nwarps * 32) {
#pragma unroll
        for (int t = 0; t < 32; t++) {
            float2 hv = *(const float2 *)(gh + (size_t)(i0 + t) * HH + 2 * lane);
            buf[t * 40 + sl] = packh(hv.x, hv.y);
        }
        __syncwarp();
        float acc[2][8][4];
        zacc(acc);
        gemmH<40, 40, 4>(acc, buf, smu + PR_AT, g, q);
#pragma unroll
        for (int m = 0; m < 2; m++) {
            int r0 = 16 * m + g, r1 = r0 + 8;
#pragma unroll
            for (int n = 0; n < 8; n++) {
                int w = 4 * n + q;
                float2 bb = *(const float2 *)(sm + PR_EB1 + 2 * w);
                g_ah[(size_t)(i0 + r0) * 32 + w] =
                    __floats2half2_rn(acc[m][n][0] + bb.x, acc[m][n][1] + bb.y);
                g_ah[(size_t)(i0 + r1) * 32 + w] =
                    __floats2half2_rn(acc[m][n][2] + bb.x, acc[m][n][3] + bb.y);
            }
        }
        zacc(acc);
        gemmH<40, 40, 4>(acc, buf, smu + PR_BT, g, q);
#pragma unroll
        for (int m = 0; m < 2; m++) {
            int r0 = 16 * m + g, r1 = r0 + 8;
#pragma unroll
            for (int n = 0; n < 8; n++) {
                int w = 4 * n + q;
                g_bh[(size_t)(i0 + r0) * 32 + w] =
                    __floats2half2_rn(acc[m][n][0], acc[m][n][1]);
                g_bh[(size_t)(i0 + r1) * 32 + w] =
                    __floats2half2_rn(acc[m][n][2], acc[m][n][3]);
            }
        }
        __syncwarp();
    }
}

// ---------------- edge kernel (f16-acc TC, h2 phase-1, red4 epilogue) ------
#define E_W2T 0
#define E_C1T 2560
#define E_B2H 5120
#define E_CB1H 5152
#define E_C2H 5184
#define E_W129H 5216
#define E_CB2 5248
#define E_WARP 5252
#define E_WARP_WORDS 1312   /* m1s 1280 + cwbuf 32 */
#define EDGE_SMEM_BYTES ((E_WARP + 8 * E_WARP_WORDS) * 4)

__global__ void __launch_bounds__(256, 3)
edge_kernel(const int *__restrict__ ei, const float *__restrict__ W1,
            const float *__restrict__ W2, const float *__restrict__ B2,
            const float *__restrict__ C1, const float *__restrict__ Cb1,
            const float *__restrict__ C2, const float *__restrict__ Cb2) {
    extern __shared__ float sm[];
    uint32_t *smu = (uint32_t *)sm;
    int tid = threadIdx.x;

    stage_w16_colperm(smu + E_W2T, W2, tid, 256);
    stage_w16_kperm(smu + E_C1T, C1, tid, 256);
    if (tid < 32) {
        // b2 in permuted fragment order: word u covers frag cols (8n+2q, +1)
        int c0 = 8 * (tid >> 2) + 2 * (tid & 3);
        int p0 = physcol(c0);
        smu[E_B2H + tid] = packh(B2[p0], B2[p0 + 1]);
        smu[E_CB1H + tid] = packh(Cb1[2 * tid], Cb1[2 * tid + 1]);
        smu[E_C2H + tid] = packh(C2[2 * tid], C2[2 * tid + 1]);
        smu[E_W129H + tid] = packh(W1[8192 + 2 * tid], W1[8192 + 2 * tid + 1]);
    }
    if (tid == 0) sm[E_CB2] = Cb2[0];
    __syncthreads();

    const int lane = tid & 31;
    const int wid = tid >> 5;
    const int g = lane >> 2;
    const int q = lane & 3;
    uint32_t *m1s = smu + E_WARP + wid * E_WARP_WORDS;
    float *cwbuf = sm + E_WARP + wid * E_WARP_WORDS + 1280;
    const int sl = pslot(lane);

    float *gagg = (float *)g_agg4;
    const uint32_t *gau = (const uint32_t *)g_ah;
    const uint32_t *gbu = (const uint32_t *)g_bh;

    const uint32_t w129h = smu[E_W129H + lane];
    const float cb2v = sm[E_CB2];

    int gwarp = blockIdx.x * 8 + wid;
    int nwarps = gridDim.x * 8;

    for (int eb = gwarp * 32; eb < NE; eb += nwarps * 32) {
        int e = eb + lane;
        int s = ei[e];
        int d = ei[NE + e];
        float4 xd = g_x4[d];
        float4 xs = g_x4[s];
        float ax = xd.x - xs.x;
        float ay = xd.y - xs.y;
        float az = xd.z - xs.z;
        float d2 = ax * ax + ay * ay + az * az;
        uint32_t d2h = packh(d2, d2);

        // phase 1 (all-h2): m1 = silu_h2(a[d] + b[s] + d2*w129)
#pragma unroll
        for (int t = 0; t < 32; t++) {
            int dt = __shfl_sync(0xffffffffu, d, t);
            int st = __shfl_sync(0xffffffffu, s, t);
            uint32_t d2t = __shfl_sync(0xffffffffu, d2h, t);
            uint32_t av = gau[(size_t)dt * 32 + lane];
            uint32_t bv = gbu[(size_t)st * 32 + lane];
            uint32_t ef = hfma2u(d2t, w129h, hadd2u(av, bv));
            m1s[t * 40 + sl] = silu_h2(ef);
        }
        __syncwarp();

        // GEMM2 (f16 acc): frag col c holds output physcol(c)
        uint32_t acc[2][8][2];
        zacc16(acc);
        gemmH16<40, 40, 4>(acc, m1s, smu + E_W2T, g, q);

        // epilogue: bias+silu in h2; agg scatter via 16B-contig red4
        uint32_t mreg[2][8][2];
#pragma unroll
        for (int m = 0; m < 2; m++) {
            int r0 = 16 * m + g;
            int r1 = r0 + 8;
            int d0 = __shfl_sync(0xffffffffu, d, r0);
            int d1 = __shfl_sync(0xffffffffu, d, r1);
            float *agg0 = gagg + (size_t)d0 * HH;
            float *agg1 = gagg + (size_t)d1 * HH;
#pragma unroll
            for (int P = 0; P < 4; P++) {
                int n0 = 2 * P, n1 = n0 + 1;
                uint32_t b0h = smu[E_B2H + 4 * n0 + q];
                uint32_t b1h = smu[E_B2H + 4 * n1 + q];
                uint32_t v00 = silu_h2(hadd2u(acc[m][n0][0], b0h));
                uint32_t v10 = silu_h2(hadd2u(acc[m][n1][0], b1h));
                uint32_t v01 = silu_h2(hadd2u(acc[m][n0][1], b0h));
                uint32_t v11 = silu_h2(hadd2u(acc[m][n1][1], b1h));
                float2 f00 = h2f2(v00), f10 = h2f2(v10);
                float2 f01 = h2f2(v01), f11 = h2f2(v11);
                int cc = 16 * P + 4 * q;
                red4(agg0 + cc, f00.x, f00.y, f10.x, f10.y);
                red4(agg1 + cc, f01.x, f01.y, f11.x, f11.y);
                mreg[m][n0][0] = v00;
                mreg[m][n0][1] = v01;
                mreg[m][n1][0] = v10;
                mreg[m][n1][1] = v11;
            }
        }

        // coord MLP (f16 acc): C1 staged with matching K perm
        zacc16(acc);
        gemmR16<40>(acc, mreg, smu + E_C1T, g, q);

        float cwp[2][2] = {{0.f, 0.f}, {0.f, 0.f}};
#pragma unroll
        for (int m = 0; m < 2; m++)
#pragma unroll
            for (int n = 0; n < 8; n++) {
                uint32_t cb1h = smu[E_CB1H + 4 * n + q];
                uint32_t c2h = smu[E_C2H + 4 * n + q];
                uint32_t p0 = hmul2u(silu_h2(hadd2u(acc[m][n][0], cb1h)), c2h);
                uint32_t p1 = hmul2u(silu_h2(hadd2u(acc[m][n][1], cb1h)), c2h);
                float2 f0 = h2f2(p0);
                float2 f1 = h2f2(p1);
                cwp[m][0] += f0.x + f0.y;
                cwp[m][1] += f1.x + f1.y;
            }
#pragma unroll
        for (int ofs = 1; ofs <= 2; ofs <<= 1) {
#pragma unroll
            for (int m = 0; m < 2; m++) {
                cwp[m][0] += __shfl_xor_sync(0xffffffffu, cwp[m][0], ofs);
                cwp[m][1] += __shfl_xor_sync(0xffffffffu, cwp[m][1], ofs);
            }
        }
        if (q == 0) {
#pragma unroll
            for (int m = 0; m < 2; m++) {
                cwbuf[16 * m + g] = cwp[m][0] + cb2v;
                cwbuf[16 * m + g + 8] = cwp[m][1] + cb2v;
            }
        }
        __syncwarp();

        float cw = cwbuf[lane];
        red4((float *)&g_dx4[d], ax * cw, ay * cw, az * cw, 0.f);
        __syncwarp();
    }
}

// ---------------- node kernel (fp32-acc TC, split-K, reg A-reuse) ----------
#define ND_W1A 0
#define ND_W1B 2560
#define ND_W2T 5120
#define ND_AT 7680
#define ND_BT 10240
#define ND_NB1 12800
#define ND_NB2 12864
#define ND_EB1 12928
#define ND_WARP 12992
#define ND_WARP_WORDS 1280
#define NODE_SMEM_BYTES ((ND_WARP + 8 * ND_WARP_WORDS) * 4)

__global__ void __launch_bounds__(256, 2)
node_kernel(float *__restrict__ xout, const float *__restrict__ NW1,
            const float *__restrict__ NB1, const float *__restrict__ NW2,
            const float *__restrict__ NB2, const float *__restrict__ EW1n,
            const float *__restrict__ EB1n, int do_pre) {
    extern __shared__ float sm[];
    uint32_t *smu = (uint32_t *)sm;
    int tid = threadIdx.x;

    stage_w16(smu + ND_W1A, NW1, 32, 40, tid, 256);           // nf rows 0..63 (h)
    stage_w16(smu + ND_W1B, NW1 + 64 * 64, 32, 40, tid, 256); // rows 64..127 (agg)
    stage_w16(smu + ND_W2T, NW2, 32, 40, tid, 256);
    if (do_pre) {
        stage_w16(smu + ND_AT, EW1n, 32, 40, tid, 256);
        stage_w16(smu + ND_BT, EW1n + 64 * 64, 32, 40, tid, 256);
    }
    cp_s(sm + ND_NB1, NB1, 64, tid, 256);
    cp_s(sm + ND_NB2, NB2, 64, tid, 256);
    if (do_pre) cp_s(sm + ND_EB1, EB1n, 64, tid, 256);
    __syncthreads();

    const int lane = tid & 31, wid = tid >> 5;
    const int g = lane >> 2, q = lane & 3;
    uint32_t *buf = smu + ND_WARP + wid * ND_WARP_WORDS;
    const int sl = pslot(lane);

    float *gh = (float *)g_h4;
    float *gagg = (float *)g_agg4;
    uint32_t *gau = (uint32_t *)g_ah;
    uint32_t *gbu = (uint32_t *)g_bh;

    int gwarp = blockIdx.x * 8 + wid;
    int nwarps = gridDim.x * 8;

    for (int i0 = gwarp * 32; i0 < NN; i0 += nwarps * 32) {
        // stage h fp16 (stride 40)
#pragma unroll
        for (int t = 0; t < 32; t++) {
            float2 hv = *(const float2 *)(gh + (size_t)(i0 + t) * HH + 2 * lane);
            buf[t * 40 + sl] = packh(hv.x, hv.y);
        }
        __syncwarp();

        float acc[2][8][4];
        zacc(acc);
        gemmH<40, 40, 4>(acc, buf, smu + ND_W1A, g, q);
        __syncwarp();

        // stage agg fp16 (overwrite h staging); zero agg
#pragma unroll
        for (int t = 0; t < 32; t++) {
            size_t ro = (size_t)(i0 + t) * HH;
            float2 av = *(const float2 *)(gagg + ro + 2 * lane);
            *(float2 *)(gagg + ro + 2 * lane) = make_float2(0.f, 0.f);
            buf[t * 40 + sl] = packh(av.x, av.y);
        }
        __syncwarp();
        gemmH<40, 40, 4>(acc, buf, smu + ND_W1B, g, q);  // accumulate
        __syncwarp();

        // m1 = silu(acc + nb1) -> A-fragments in registers
        uint32_t mreg[2][8][2];
#pragma unroll
        for (int m = 0; m < 2; m++) {
#pragma unroll
            for (int n = 0; n < 8; n++) {
                int c0 = 8 * n + 2 * q;
                float2 bb = *(const float2 *)(sm + ND_NB1 + c0);
                mreg[m][n][0] = packh(siluf(acc[m][n][0] + bb.x),
                                      siluf(acc[m][n][1] + bb.y));
                mreg[m][n][1] = packh(siluf(acc[m][n][2] + bb.x),
                                      siluf(acc[m][n][3] + bb.y));
            }
        }

        zacc(acc);
        gemmR<40>(acc, mreg, smu + ND_W2T, g, q);

        // hnew = h_old + acc + nb2 -> global; pack hnew for pre gemms
#pragma unroll
        for (int m = 0; m < 2; m++) {
            int r0 = 16 * m + g, r1 = r0 + 8;
            float *h0 = gh + (size_t)(i0 + r0) * HH;
            float *h1 = gh + (size_t)(i0 + r1) * HH;
#pragma unroll
            for (int n = 0; n < 8; n++) {
                int c0 = 8 * n + 2 * q;
                float2 bb = *(const float2 *)(sm + ND_NB2 + c0);
                float2 o0 = *(const float2 *)(h0 + c0);
                float2 o1 = *(const float2 *)(h1 + c0);
                o0.x += acc[m][n][0] + bb.x;
                o0.y += acc[m][n][1] + bb.y;
                o1.x += acc[m][n][2] + bb.x;
                o1.y += acc[m][n][3] + bb.y;
                *(float2 *)(h0 + c0) = o0;
                *(float2 *)(h1 + c0) = o1;
                if (do_pre) {
                    mreg[m][n][0] = packh(o0.x, o0.y);
                    mreg[m][n][1] = packh(o1.x, o1.y);
                }
            }
        }

        if (do_pre) {
            zacc(acc);
            gemmR<40>(acc, mreg, smu + ND_AT, g, q);
#pragma unroll
            for (int m = 0; m < 2; m++) {
                int r0 = 16 * m + g, r1 = r0 + 8;
#pragma unroll
                for (int n = 0; n < 8; n++) {
                    int w = 4 * n + q;
                    float2 bb = *(const float2 *)(sm + ND_EB1 + 2 * w);
                    gau[(size_t)(i0 + r0) * 32 + w] =
                        packh(acc[m][n][0] + bb.x, acc[m][n][1] + bb.y);
                    gau[(size_t)(i0 + r1) * 32 + w] =
                        packh(acc[m][n][2] + bb.x, acc[m][n][3] + bb.y);
                }
            }
            zacc(acc);
            gemmR<40>(acc, mreg, smu + ND_BT, g, q);
#pragma unroll
            for (int m = 0; m < 2; m++) {
                int r0 = 16 * m + g, r1 = r0 + 8;
#pragma unroll
                for (int n = 0; n < 8; n++) {
                    int w = 4 * n + q;
                    gbu[(size_t)(i0 + r0) * 32 + w] =
                        packh(acc[m][n][0], acc[m][n][1]);
                    gbu[(size_t)(i0 + r1) * 32 + w] =
                        packh(acc[m][n][2], acc[m][n][3]);
                }
            }
        }

        // x += dx; update padded coords; reset dx (lane = node)
        int i = i0 + lane;
        float4 dxv = g_dx4[i];
        g_dx4[i] = make_float4(0.f, 0.f, 0.f, 0.f);
        float4 xv = g_x4[i];
        xv.x += dxv.x;
        xv.y += dxv.y;
        xv.z += dxv.z;
        g_x4[i] = xv;
        xout[3 * i + 0] = xv.x;
        xout[3 * i + 1] = xv.y;
        xout[3 * i + 2] = xv.z;
        __syncwarp();
    }
}

// ---------------- launch ----------------
extern "C" void kernel_launch(void *const *d_in, const int *in_sizes, int n_in,
                              void *d_out, int out_size) {
    const float *x   = (const float *)d_in[0];
    const int   *z   = (const int *)d_in[1];
    const float *t   = (const float *)d_in[2];
    const int   *ei  = (const int *)d_in[3];
    const float *emb = (const float *)d_in[4];
    const float *tw1 = (const float *)d_in[5];
    const float *tb1 = (const float *)d_in[6];
    const float *tw2 = (const float *)d_in[7];
    const float *tb2 = (const float *)d_in[8];
    const float *ew1 = (const float *)d_in[9];
    const float *eb1 = (const float *)d_in[10];
    const float *ew2 = (const float *)d_in[11];
    const float *eb2 = (const float *)d_in[12];
    const float *cw1 = (const float *)d_in[13];
    const float *cb1 = (const float *)d_in[14];
    const float *cw2 = (const float *)d_in[15];
    const float *cb2 = (const float *)d_in[16];
    const float *nw1 = (const float *)d_in[17];
    const float *nb1 = (const float *)d_in[18];
    const float *nw2 = (const float *)d_in[19];
    const float *nb2 = (const float *)d_in[20];
    float *out = (float *)d_out;

    cudaFuncSetAttribute(edge_kernel, cudaFuncAttributeMaxDynamicSharedMemorySize,
                         EDGE_SMEM_BYTES);
    cudaFuncSetAttribute(node_kernel, cudaFuncAttributeMaxDynamicSharedMemorySize,
                         NODE_SMEM_BYTES);
    cudaFuncSetAttribute(pre0_kernel, cudaFuncAttributeMaxDynamicSharedMemorySize,
                         PRE_SMEM_BYTES);

    tmean_kernel<<<1, 64>>>(t, tw1, tb1, tw2, tb2);
    init_kernel<<<2048, 256>>>(x, z, emb, out);
    pre0_kernel<<<296, 256, PRE_SMEM_BYTES>>>(ew1, eb1);
    for (int l = 0; l < NLAYERS; l++) {
        edge_kernel<<<444, 256, EDGE_SMEM_BYTES>>>(
            ei, ew1 + l * 8256, ew2 + l * 4096, eb2 + l * 64,
            cw1 + l * 4096, cb1 + l * 64, cw2 + l * 64, cb2 + l);
        int do_pre = (l + 1 < NLAYERS);
        node_kernel<<<296, 256, NODE_SMEM_BYTES>>>(
            out, nw1 + l * 8192, nb1 + l * 64, nw2 + l * 4096, nb2 + l * 64,
            do_pre ? (ew1 + (l + 1) * 8256) : ew1,
            do_pre ? (eb1 + (l + 1) * 64) : eb1, do_pre);
    }
    (void)in_sizes; (void)n_in; (void)out_size;
}